// round 2
// baseline (speedup 1.0000x reference)
#include <cuda_runtime.h>
#include <math.h>
#include <stdint.h>

#define Bb 8
#define Nn 1024
#define HIDD 256
#define HEADS 8
#define DHH 32
#define KPOOL 512
#define EPER 16384
#define INVKEY (KPOOL*KPOOL)      // 262144
#define BINS (INVKEY+1)           // 262145
#define CHUNK 2048
#define NCH 129                   // ceil(BINS/CHUNK)

// ---------------- scratch (static device globals; no runtime alloc) -------------
__device__ float g_q  [Bb*Nn*HIDD];        // Q; later reused as encoder output
__device__ float g_kT [Bb*HEADS*DHH*Nn];   // [b,h,d,n]
__device__ float g_vT [Bb*HEADS*DHH*Nn];   // [b,h,d,n]
__device__ float g_att[Bb*Nn*HIDD];
__device__ float g_sval[Bb*Nn];
__device__ int   g_perm[Bb*KPOOL];
__device__ float g_vals[Bb*KPOOL];
__device__ int   g_nmap[Bb*Nn];
__device__ unsigned g_key[Bb*EPER];
__device__ int   g_nu[Bb*EPER];
__device__ int   g_nv[Bb*EPER];
__device__ unsigned g_cnt  [Bb*BINS];
__device__ unsigned g_scan [Bb*BINS];
__device__ unsigned g_chunk  [Bb*NCH];
__device__ unsigned g_chunkEx[Bb*NCH];
__device__ int   g_is64;

// output layout (elements, concatenated in reference return order)
#define OFF_ENC   ((long long)0)
#define OFF_SUBX  ((long long)2097152)
#define OFF_EDGE  ((long long)3145728)
#define OFF_PERM  ((long long)3407872)
#define OFF_VALID ((long long)3411968)

// bounds-checked, dtype-adaptive output store
__device__ __forceinline__ void st_out(void* out, long long idx, float v,
                                       long long osz) {
    if (idx < 0 || idx >= osz) return;
    if (g_is64) ((double*)out)[idx] = (double)v;
    else        ((float*) out)[idx] = v;
}

// ---------------- input dtype probe ---------------------------------------------
__global__ void detect_k(const int* __restrict__ e32) {
    // int64 edge_index (nonneg small values) => odd 32-bit words are 0
    g_is64 = (e32[1] == 0 && e32[3] == 0 && e32[5] == 0 && e32[7] == 0) ? 1 : 0;
}

// ---------------- GEMM: C[M,256] = A[M,256] @ W[256,256] ------------------------
// MODE 0: row-major store.  MODE 1: store transposed to [b,h,d,n].
// DST: 0=g_q  1=g_kT  2=g_vT  3=g_q (encoder reuse).  A==nullptr => read g_att.
template<int MODE, int DST>
__global__ void sgemm_k(const float* __restrict__ A_in, const float* __restrict__ W) {
    const float* A = (A_in != nullptr) ? A_in : g_att;
    float* C = (DST == 1) ? g_kT : (DST == 2) ? g_vT : g_q;
    __shared__ float As[16][65];
    __shared__ float Ws[16][64];
    const int bm = blockIdx.x * 64, bn = blockIdx.y * 64;
    const int tid = threadIdx.x;
    const int tx = tid & 15, ty = tid >> 4;
    float acc[4][4];
#pragma unroll
    for (int i = 0; i < 4; i++)
#pragma unroll
        for (int j = 0; j < 4; j++) acc[i][j] = 0.f;

    for (int kk = 0; kk < HIDD; kk += 16) {
        {
            int m = tid >> 2, kq = tid & 3;
            float4 av = *(const float4*)&A[(size_t)(bm + m) * HIDD + kk + kq * 4];
            As[kq*4+0][m] = av.x; As[kq*4+1][m] = av.y;
            As[kq*4+2][m] = av.z; As[kq*4+3][m] = av.w;
        }
        {
            int k = tid >> 4, nq = tid & 15;
            *(float4*)&Ws[k][nq*4] =
                *(const float4*)&W[(size_t)(kk + k) * HIDD + bn + nq * 4];
        }
        __syncthreads();
#pragma unroll
        for (int k = 0; k < 16; k++) {
            float a0 = As[k][ty*4+0], a1 = As[k][ty*4+1];
            float a2 = As[k][ty*4+2], a3 = As[k][ty*4+3];
            float4 b4 = *(float4*)&Ws[k][tx*4];
            acc[0][0] += a0*b4.x; acc[0][1] += a0*b4.y; acc[0][2] += a0*b4.z; acc[0][3] += a0*b4.w;
            acc[1][0] += a1*b4.x; acc[1][1] += a1*b4.y; acc[1][2] += a1*b4.z; acc[1][3] += a1*b4.w;
            acc[2][0] += a2*b4.x; acc[2][1] += a2*b4.y; acc[2][2] += a2*b4.z; acc[2][3] += a2*b4.w;
            acc[3][0] += a3*b4.x; acc[3][1] += a3*b4.y; acc[3][2] += a3*b4.z; acc[3][3] += a3*b4.w;
        }
        __syncthreads();
    }
    if (MODE == 0) {
#pragma unroll
        for (int i = 0; i < 4; i++) {
            int row = bm + ty*4 + i;
            float4 v = make_float4(acc[i][0], acc[i][1], acc[i][2], acc[i][3]);
            *(float4*)&C[(size_t)row * HIDD + bn + tx*4] = v;
        }
    } else {
#pragma unroll
        for (int i = 0; i < 4; i++) {
            int row = bm + ty*4 + i;
            int b = row >> 10, n = row & 1023;
#pragma unroll
            for (int j = 0; j < 4; j++) {
                int col = bn + tx*4 + j;
                int h = col >> 5, d = col & 31;
                C[(size_t)(((b << 3) + h) * DHH + d) * Nn + n] = acc[i][j];
            }
        }
    }
}

// ---------------- flash attention (f32, online softmax, +dist bias) -------------
__global__ void attn_k(const float* __restrict__ dist) {
    __shared__ float Qs[32][32];
    __shared__ float KT[32][132];
    __shared__ float VT[32][132];
    __shared__ float pbuf[8][128];
    const int bh = blockIdx.x;            // b*8+h
    const int b = bh >> 3;
    const int qbase = blockIdx.y * 32;
    const int tid = threadIdx.x, lane = tid & 31, warp = tid >> 5;
    const int h = bh & 7;

    {
        int rl = tid >> 3, dq = tid & 7;
        *(float4*)&Qs[rl][dq*4] =
            *(const float4*)&g_q[((size_t)(b * Nn) + (qbase + rl)) * HIDD + h * DHH + dq * 4];
    }
    float m[4], l[4], acc[4];
#pragma unroll
    for (int r = 0; r < 4; r++) { m[r] = -1e30f; l[r] = 0.f; acc[r] = 0.f; }
    __syncthreads();

    const float isq = 0.17677669529663687f; // 1/sqrt(32)
    for (int kt = 0; kt < 8; kt++) {
        const int k0 = kt * 128;
        __syncthreads();
#pragma unroll
        for (int i = 0; i < 4; i++) {
            int F = tid + i * 256;
            int d = F >> 5, kq = F & 31;
            size_t gidx = ((size_t)(bh * DHH) + d) * Nn + k0 + kq * 4;
            *(float4*)&KT[d][kq*4] = *(const float4*)&g_kT[gidx];
            *(float4*)&VT[d][kq*4] = *(const float4*)&g_vT[gidx];
        }
        __syncthreads();

        for (int r = 0; r < 4; r++) {
            const int rl = warp * 4 + r;
            const int row = qbase + rl;
            float qr[32];
#pragma unroll
            for (int d = 0; d < 32; d++) qr[d] = Qs[rl][d];

            float4 s4 = make_float4(0.f, 0.f, 0.f, 0.f);
#pragma unroll
            for (int d = 0; d < 32; d++) {
                float4 kv = *(float4*)&KT[d][lane*4];
                s4.x += qr[d]*kv.x; s4.y += qr[d]*kv.y;
                s4.z += qr[d]*kv.z; s4.w += qr[d]*kv.w;
            }
            float4 dv = *(const float4*)&dist[((size_t)(b * Nn + row)) * Nn + k0 + lane * 4];
            s4.x = s4.x*isq + dv.x; s4.y = s4.y*isq + dv.y;
            s4.z = s4.z*isq + dv.z; s4.w = s4.w*isq + dv.w;

            float tmax = fmaxf(fmaxf(s4.x, s4.y), fmaxf(s4.z, s4.w));
#pragma unroll
            for (int o = 16; o; o >>= 1) tmax = fmaxf(tmax, __shfl_xor_sync(0xffffffffu, tmax, o));
            float mn = fmaxf(m[r], tmax);
            float corr = __expf(m[r] - mn);
            float4 p4;
            p4.x = __expf(s4.x - mn); p4.y = __expf(s4.y - mn);
            p4.z = __expf(s4.z - mn); p4.w = __expf(s4.w - mn);
            float ps = p4.x + p4.y + p4.z + p4.w;
#pragma unroll
            for (int o = 16; o; o >>= 1) ps += __shfl_xor_sync(0xffffffffu, ps, o);
            l[r] = l[r] * corr + ps;
            m[r] = mn;
            acc[r] *= corr;

            *(float4*)&pbuf[warp][lane*4] = p4;
            __syncwarp();
            float a = acc[r];
#pragma unroll
            for (int k4 = 0; k4 < 32; k4++) {
                float4 pv = *(float4*)&pbuf[warp][k4*4];
                float4 vv = *(float4*)&VT[lane][k4*4];
                a += pv.x*vv.x + pv.y*vv.y + pv.z*vv.z + pv.w*vv.w;
            }
            acc[r] = a;
            __syncwarp();
        }
    }
#pragma unroll
    for (int r = 0; r < 4; r++) {
        int row = qbase + warp * 4 + r;
        g_att[((size_t)(b * Nn) + row) * HIDD + h * DHH + lane] = acc[r] / l[r];
    }
}

// ---------------- pack encoder result to output ---------------------------------
__global__ void pack_k(void* __restrict__ out, long long osz) {
    long long i = (long long)blockIdx.x * blockDim.x + threadIdx.x;
    if (i < (long long)Bb * Nn * HIDD) st_out(out, OFF_ENC + i, g_q[i], osz);
}

// ---------------- tanh projection scores ---------------------------------------
__global__ void score_k(const float* __restrict__ w) {
    int gw = (blockIdx.x * blockDim.x + threadIdx.x) >> 5;
    int lane = threadIdx.x & 31;
    if (gw >= Bb * Nn) return;
    float nw = 0.f, dot = 0.f;
#pragma unroll
    for (int i = 0; i < 8; i++) {
        float wv = w[lane + i * 32];
        nw += wv * wv;
        dot += wv * g_q[(size_t)gw * HIDD + lane + i * 32];
    }
#pragma unroll
    for (int o = 16; o; o >>= 1) {
        nw  += __shfl_xor_sync(0xffffffffu, nw, o);
        dot += __shfl_xor_sync(0xffffffffu, dot, o);
    }
    if (lane == 0) g_sval[gw] = tanhf(dot / sqrtf(nw));
}

// ---------------- per-graph top-k (full bitonic sort of 1024) -------------------
__global__ void topk_k(void* __restrict__ out, long long osz) {
    __shared__ unsigned long long keys[1024];
    const int b = blockIdx.x, t = threadIdx.x;
    float s = g_sval[b * Nn + t];
    unsigned u = __float_as_uint(s);
    u = (u & 0x80000000u) ? ~u : (u | 0x80000000u);
    u = ~u;
    keys[t] = ((unsigned long long)u << 32) | (unsigned)t;
    __syncthreads();
    for (int k = 2; k <= 1024; k <<= 1) {
        for (int j = k >> 1; j > 0; j >>= 1) {
            int ixj = t ^ j;
            if (ixj > t) {
                bool up = ((t & k) == 0);
                unsigned long long a = keys[t], bv = keys[ixj];
                if ((a > bv) == up) { keys[t] = bv; keys[ixj] = a; }
            }
            __syncthreads();
        }
    }
    g_nmap[b * Nn + t] = -1;
    __syncthreads();
    if (t < KPOOL) {
        int idx = (int)(keys[t] & 0xffffffffu);
        g_perm[b * KPOOL + t] = idx;
        g_vals[b * KPOOL + t] = g_sval[b * Nn + idx];
        g_nmap[b * Nn + idx] = t;
        st_out(out, OFF_PERM + b * KPOOL + t, (float)idx, osz);
    }
}

// ---------------- gated gather sub_x --------------------------------------------
__global__ void subx_k(void* __restrict__ out, long long osz) {
    long long idx = (long long)blockIdx.x * blockDim.x + threadIdx.x;
    int c = (int)(idx & 255);
    int r = (int)((idx >> 8) & 511);
    int b = (int)(idx >> 17);
    int p = g_perm[b * KPOOL + r];
    float v = g_q[((size_t)(b * Nn) + p) * HIDD + c] * g_vals[b * KPOOL + r];
    st_out(out, OFF_SUBX + idx, v, osz);
}

// ---------------- edge pipeline --------------------------------------------------
__global__ void zero_k() {
    int i = blockIdx.x * blockDim.x + threadIdx.x;
    if (i < Bb * BINS) g_cnt[i] = 0u;
}

__global__ void edge_k(const void* __restrict__ ei) {
    int e = blockIdx.x * blockDim.x + threadIdx.x;
    if (e >= Bb * EPER) return;
    int b = e >> 14;
    long long sv, dvv;
    if (g_is64) {
        const long long* p = (const long long*)ei;
        sv = p[e]; dvv = p[Bb * EPER + e];
    } else {
        const int* p = (const int*)ei;
        sv = p[e]; dvv = p[Bb * EPER + e];
    }
    int ls = (int)(sv - (long long)b * Nn);
    int ld = (int)(dvv - (long long)b * Nn);
    bool inr = (ls >= 0) && (ls < Nn) && (ld >= 0) && (ld < Nn);
    int nu = inr ? g_nmap[b * Nn + ls] : -1;
    int nv = inr ? g_nmap[b * Nn + ld] : -1;
    bool valid = (nu >= 0) && (nv >= 0);
    unsigned key = valid ? (unsigned)(nu * KPOOL + nv) : (unsigned)INVKEY;
    g_key[e] = key; g_nu[e] = nu; g_nv[e] = nv;
    atomicAdd(&g_cnt[(size_t)b * BINS + key], 1u);
}

__global__ void scan1_k() {
    __shared__ unsigned sh[1024];
    const int b = blockIdx.x, c = blockIdx.y, t = threadIdx.x;
    int i0 = c * CHUNK + t * 2;
    unsigned v0 = (i0     < BINS) ? g_cnt[(size_t)b * BINS + i0]     : 0u;
    unsigned v1 = (i0 + 1 < BINS) ? g_cnt[(size_t)b * BINS + i0 + 1] : 0u;
    sh[t] = v0 + v1;
    __syncthreads();
    for (int off = 1; off < 1024; off <<= 1) {
        unsigned x = (t >= off) ? sh[t - off] : 0u;
        __syncthreads();
        sh[t] += x;
        __syncthreads();
    }
    unsigned excl = t ? sh[t - 1] : 0u;
    if (i0     < BINS) g_scan[(size_t)b * BINS + i0]     = excl;
    if (i0 + 1 < BINS) g_scan[(size_t)b * BINS + i0 + 1] = excl + v0;
    if (t == 1023) g_chunk[b * NCH + c] = sh[1023];
}

__global__ void scan2_k() {
    int b = threadIdx.x;
    if (b >= Bb) return;
    unsigned run = 0;
    for (int c = 0; c < NCH; c++) {
        unsigned v = g_chunk[b * NCH + c];
        g_chunkEx[b * NCH + c] = run;
        run += v;
    }
}

__global__ void scatter_k(void* __restrict__ out, long long osz) {
    __shared__ unsigned sh[1024];
    const int b = blockIdx.x, t = threadIdx.x;
    const int gb = b * EPER;
    const int i0 = t * 16;
    unsigned cinv = 0;
#pragma unroll
    for (int u = 0; u < 16; u++) cinv += (g_key[gb + i0 + u] == (unsigned)INVKEY);
    sh[t] = cinv;
    __syncthreads();
    for (int off = 1; off < 1024; off <<= 1) {
        unsigned x = (t >= off) ? sh[t - off] : 0u;
        __syncthreads();
        sh[t] += x;
        __syncthreads();
    }
    unsigned invBase = t ? sh[t - 1] : 0u;
    unsigned nValid = g_scan[(size_t)b * BINS + INVKEY] + g_chunkEx[b * NCH + INVKEY / CHUNK];
    unsigned run = invBase;
    for (int u = 0; u < 16; u++) {
        int i = i0 + u;
        unsigned key = g_key[gb + i];
        bool valid = (key != (unsigned)INVKEY);
        unsigned pos;
        if (!valid) {
            pos = nValid + run; run++;
        } else {
            unsigned base = g_scan[(size_t)b * BINS + key] + g_chunkEx[b * NCH + key / CHUNK];
            unsigned cnt  = g_cnt[(size_t)b * BINS + key];
            unsigned rank = 0;
            if (cnt > 1) {
                for (int j = 0; j < i; j++) rank += (g_key[gb + j] == key);
            }
            pos = base + rank;
        }
        int nu = g_nu[gb + i], nv = g_nv[gb + i];
        st_out(out, OFF_EDGE + (long long)(b * 2 + 0) * EPER + pos,
               valid ? (float)nu : -1.0f, osz);
        st_out(out, OFF_EDGE + (long long)(b * 2 + 1) * EPER + pos,
               valid ? (float)nv : -1.0f, osz);
        st_out(out, OFF_VALID + (long long)b * EPER + pos,
               valid ? 1.0f : 0.0f, osz);
    }
}

// ---------------- launch ---------------------------------------------------------
extern "C" void kernel_launch(void* const* d_in, const int* in_sizes, int n_in,
                              void* d_out, int out_size) {
    const float* x    = (const float*)d_in[0];
    const void*  ei   = d_in[1];
    const float* dist = (const float*)d_in[3];
    const float* Wq   = (const float*)d_in[5];
    const float* Wk   = (const float*)d_in[6];
    const float* Wv   = (const float*)d_in[7];
    const float* Wo   = (const float*)d_in[8];
    const float* tw   = (const float*)d_in[9];
    long long osz = (long long)out_size;

    detect_k<<<1, 1>>>((const int*)ei);

    dim3 gG(128, 4);
    sgemm_k<0,0><<<gG, 256>>>(x, Wq);          // Q -> g_q
    sgemm_k<1,1><<<gG, 256>>>(x, Wk);          // K -> g_kT [b,h,d,n]
    sgemm_k<1,2><<<gG, 256>>>(x, Wv);          // V -> g_vT [b,h,d,n]
    attn_k<<<dim3(64, 32), 256>>>(dist);       // -> g_att
    sgemm_k<0,3><<<gG, 256>>>(nullptr, Wo);    // g_att @ Wo -> g_q (encoder out)

    pack_k<<<2048, 1024>>>(d_out, osz);
    zero_k<<<2049, 1024>>>();
    score_k<<<1024, 256>>>(tw);
    topk_k<<<8, 1024>>>(d_out, osz);
    subx_k<<<4096, 256>>>(d_out, osz);
    edge_k<<<512, 256>>>(ei);
    scan1_k<<<dim3(8, 129), 1024>>>();
    scan2_k<<<1, 32>>>();
    scatter_k<<<8, 1024>>>(d_out, osz);
}

// round 3
// speedup vs baseline: 1.6637x; 1.6637x over previous
#include <cuda_runtime.h>
#include <math.h>
#include <stdint.h>

#define Bb 8
#define Nn 1024
#define HIDD 256
#define HEADS 8
#define DHH 32
#define KPOOL 512
#define EPER 16384
#define INVKEY (KPOOL*KPOOL)      // 262144
#define BINS (INVKEY+1)           // 262145
#define CHUNK 2048
#define NCH 129                   // ceil(BINS/CHUNK)

// ---------------- scratch (static device globals; no runtime alloc) -------------
__device__ float g_q  [Bb*Nn*HIDD];        // Q; later reused as encoder output
__device__ float g_kT [Bb*HEADS*DHH*Nn];   // [b,h,d,n]
__device__ float g_vT [Bb*HEADS*DHH*Nn];   // [b,h,d,n]
__device__ float g_att[Bb*Nn*HIDD];
__device__ float g_sval[Bb*Nn];
__device__ int   g_perm[Bb*KPOOL];
__device__ float g_vals[Bb*KPOOL];
__device__ int   g_nmap[Bb*Nn];
__device__ unsigned g_key[Bb*EPER];
__device__ int   g_nu[Bb*EPER];
__device__ int   g_nv[Bb*EPER];
__device__ unsigned g_cnt  [Bb*BINS];
__device__ unsigned g_scan [Bb*BINS];
__device__ unsigned g_chunk  [Bb*NCH];
__device__ unsigned g_chunkEx[Bb*NCH];
__device__ int   g_is64;

// output layout (elements, concatenated in reference return order)
#define OFF_ENC   ((long long)0)
#define OFF_SUBX  ((long long)2097152)
#define OFF_EDGE  ((long long)3145728)
#define OFF_PERM  ((long long)3407872)
#define OFF_VALID ((long long)3411968)

__device__ __forceinline__ void st_out(void* out, long long idx, float v,
                                       long long osz) {
    if (idx < 0 || idx >= osz) return;
    if (g_is64) ((double*)out)[idx] = (double)v;
    else        ((float*) out)[idx] = v;
}

// ---------------- input dtype probe ---------------------------------------------
__global__ void detect_k(const int* __restrict__ e32) {
    g_is64 = (e32[1] == 0 && e32[3] == 0 && e32[5] == 0 && e32[7] == 0) ? 1 : 0;
}

// ---------------- GEMM: C[M,256] = A[M,256] @ W[256,256] ------------------------
template<int MODE, int DST>
__global__ void sgemm_k(const float* __restrict__ A_in, const float* __restrict__ W) {
    const float* A = (A_in != nullptr) ? A_in : g_att;
    float* C = (DST == 1) ? g_kT : (DST == 2) ? g_vT : g_q;
    __shared__ float As[16][65];
    __shared__ float Ws[16][64];
    const int bm = blockIdx.x * 64, bn = blockIdx.y * 64;
    const int tid = threadIdx.x;
    const int tx = tid & 15, ty = tid >> 4;
    float acc[4][4];
#pragma unroll
    for (int i = 0; i < 4; i++)
#pragma unroll
        for (int j = 0; j < 4; j++) acc[i][j] = 0.f;

    for (int kk = 0; kk < HIDD; kk += 16) {
        {
            int m = tid >> 2, kq = tid & 3;
            float4 av = *(const float4*)&A[(size_t)(bm + m) * HIDD + kk + kq * 4];
            As[kq*4+0][m] = av.x; As[kq*4+1][m] = av.y;
            As[kq*4+2][m] = av.z; As[kq*4+3][m] = av.w;
        }
        {
            int k = tid >> 4, nq = tid & 15;
            *(float4*)&Ws[k][nq*4] =
                *(const float4*)&W[(size_t)(kk + k) * HIDD + bn + nq * 4];
        }
        __syncthreads();
#pragma unroll
        for (int k = 0; k < 16; k++) {
            float a0 = As[k][ty*4+0], a1 = As[k][ty*4+1];
            float a2 = As[k][ty*4+2], a3 = As[k][ty*4+3];
            float4 b4 = *(float4*)&Ws[k][tx*4];
            acc[0][0] += a0*b4.x; acc[0][1] += a0*b4.y; acc[0][2] += a0*b4.z; acc[0][3] += a0*b4.w;
            acc[1][0] += a1*b4.x; acc[1][1] += a1*b4.y; acc[1][2] += a1*b4.z; acc[1][3] += a1*b4.w;
            acc[2][0] += a2*b4.x; acc[2][1] += a2*b4.y; acc[2][2] += a2*b4.z; acc[2][3] += a2*b4.w;
            acc[3][0] += a3*b4.x; acc[3][1] += a3*b4.y; acc[3][2] += a3*b4.z; acc[3][3] += a3*b4.w;
        }
        __syncthreads();
    }
    if (MODE == 0) {
#pragma unroll
        for (int i = 0; i < 4; i++) {
            int row = bm + ty*4 + i;
            float4 v = make_float4(acc[i][0], acc[i][1], acc[i][2], acc[i][3]);
            *(float4*)&C[(size_t)row * HIDD + bn + tx*4] = v;
        }
    } else {
#pragma unroll
        for (int i = 0; i < 4; i++) {
            int row = bm + ty*4 + i;
            int b = row >> 10, n = row & 1023;
#pragma unroll
            for (int j = 0; j < 4; j++) {
                int col = bn + tx*4 + j;
                int h = col >> 5, d = col & 31;
                C[(size_t)(((b << 3) + h) * DHH + d) * Nn + n] = acc[i][j];
            }
        }
    }
}

// ---------------- flash attention (register-tiled: 4 rows per pass) -------------
__global__ void attn_k(const float* __restrict__ dist) {
    __shared__ float Qs[32][32];
    __shared__ float KT[32][132];
    __shared__ float VT[32][132];
    __shared__ float pbuf[8][4][128];
    const int bh = blockIdx.x;            // b*8+h
    const int b = bh >> 3, h = bh & 7;
    const int qbase = blockIdx.y * 32;
    const int tid = threadIdx.x, lane = tid & 31, warp = tid >> 5;
    const int r0 = warp * 4;

    {   // load Q tile [32 rows][32 dims]
        int rl = tid >> 3, dq = tid & 7;
        *(float4*)&Qs[rl][dq*4] =
            *(const float4*)&g_q[((size_t)(b * Nn) + (qbase + rl)) * HIDD + h * DHH + dq * 4];
    }
    float m[4], l[4], acc[4];
#pragma unroll
    for (int r = 0; r < 4; r++) { m[r] = -1e30f; l[r] = 0.f; acc[r] = 0.f; }
    __syncthreads();

    const float isq = 0.17677669529663687f; // 1/sqrt(32)
    for (int kt = 0; kt < 8; kt++) {
        const int k0 = kt * 128;
        __syncthreads();
#pragma unroll
        for (int i = 0; i < 4; i++) {
            int F = tid + i * 256;
            int d = F >> 5, kq = F & 31;
            size_t gidx = ((size_t)(bh * DHH) + d) * Nn + k0 + kq * 4;
            *(float4*)&KT[d][kq*4] = *(const float4*)&g_kT[gidx];
            *(float4*)&VT[d][kq*4] = *(const float4*)&g_vT[gidx];
        }
        // prefetch dist bias for this warp's 4 rows (L2 hit, overlap with QK)
        float4 dv[4];
#pragma unroll
        for (int r = 0; r < 4; r++)
            dv[r] = *(const float4*)&dist[((size_t)(b * Nn + qbase + r0 + r)) * Nn + k0 + lane * 4];
        __syncthreads();

        // QK: all 4 rows in one pass over d (KT read once per warp)
        float4 s[4];
#pragma unroll
        for (int r = 0; r < 4; r++) s[r] = make_float4(0.f, 0.f, 0.f, 0.f);
#pragma unroll
        for (int d = 0; d < 32; d++) {
            float4 kv = *(float4*)&KT[d][lane*4];
            float q0 = Qs[r0+0][d], q1 = Qs[r0+1][d];
            float q2 = Qs[r0+2][d], q3 = Qs[r0+3][d];
            s[0].x += q0*kv.x; s[0].y += q0*kv.y; s[0].z += q0*kv.z; s[0].w += q0*kv.w;
            s[1].x += q1*kv.x; s[1].y += q1*kv.y; s[1].z += q1*kv.z; s[1].w += q1*kv.w;
            s[2].x += q2*kv.x; s[2].y += q2*kv.y; s[2].z += q2*kv.z; s[2].w += q2*kv.w;
            s[3].x += q3*kv.x; s[3].y += q3*kv.y; s[3].z += q3*kv.z; s[3].w += q3*kv.w;
        }

        // online softmax per row; stash p into pbuf
#pragma unroll
        for (int r = 0; r < 4; r++) {
            float4 s4 = s[r];
            s4.x = s4.x*isq + dv[r].x; s4.y = s4.y*isq + dv[r].y;
            s4.z = s4.z*isq + dv[r].z; s4.w = s4.w*isq + dv[r].w;
            float tmax = fmaxf(fmaxf(s4.x, s4.y), fmaxf(s4.z, s4.w));
#pragma unroll
            for (int o = 16; o; o >>= 1) tmax = fmaxf(tmax, __shfl_xor_sync(0xffffffffu, tmax, o));
            float mn = fmaxf(m[r], tmax);
            float corr = __expf(m[r] - mn);
            float4 p4;
            p4.x = __expf(s4.x - mn); p4.y = __expf(s4.y - mn);
            p4.z = __expf(s4.z - mn); p4.w = __expf(s4.w - mn);
            float ps = p4.x + p4.y + p4.z + p4.w;
#pragma unroll
            for (int o = 16; o; o >>= 1) ps += __shfl_xor_sync(0xffffffffu, ps, o);
            l[r] = l[r] * corr + ps;
            m[r] = mn;
            acc[r] *= corr;
            *(float4*)&pbuf[warp][r][lane*4] = p4;
        }
        __syncwarp();

        // AV: all 4 rows in one pass over k (VT read once per warp)
#pragma unroll
        for (int k4 = 0; k4 < 32; k4++) {
            float4 vv = *(float4*)&VT[lane][k4*4];
            float4 p0 = *(float4*)&pbuf[warp][0][k4*4];
            float4 p1 = *(float4*)&pbuf[warp][1][k4*4];
            float4 p2 = *(float4*)&pbuf[warp][2][k4*4];
            float4 p3 = *(float4*)&pbuf[warp][3][k4*4];
            acc[0] += p0.x*vv.x + p0.y*vv.y + p0.z*vv.z + p0.w*vv.w;
            acc[1] += p1.x*vv.x + p1.y*vv.y + p1.z*vv.z + p1.w*vv.w;
            acc[2] += p2.x*vv.x + p2.y*vv.y + p2.z*vv.z + p2.w*vv.w;
            acc[3] += p3.x*vv.x + p3.y*vv.y + p3.z*vv.z + p3.w*vv.w;
        }
        __syncwarp();
    }
#pragma unroll
    for (int r = 0; r < 4; r++) {
        int row = qbase + r0 + r;
        g_att[((size_t)(b * Nn) + row) * HIDD + h * DHH + lane] = acc[r] / l[r];
    }
}

// ---------------- pack encoder result to output ---------------------------------
__global__ void pack_k(void* __restrict__ out, long long osz) {
    long long i = (long long)blockIdx.x * blockDim.x + threadIdx.x;
    if (i < (long long)Bb * Nn * HIDD) st_out(out, OFF_ENC + i, g_q[i], osz);
}

// ---------------- tanh projection scores ---------------------------------------
__global__ void score_k(const float* __restrict__ w) {
    int gw = (blockIdx.x * blockDim.x + threadIdx.x) >> 5;
    int lane = threadIdx.x & 31;
    if (gw >= Bb * Nn) return;
    float nw = 0.f, dot = 0.f;
#pragma unroll
    for (int i = 0; i < 8; i++) {
        float wv = w[lane + i * 32];
        nw += wv * wv;
        dot += wv * g_q[(size_t)gw * HIDD + lane + i * 32];
    }
#pragma unroll
    for (int o = 16; o; o >>= 1) {
        nw  += __shfl_xor_sync(0xffffffffu, nw, o);
        dot += __shfl_xor_sync(0xffffffffu, dot, o);
    }
    if (lane == 0) g_sval[gw] = tanhf(dot / sqrtf(nw));
}

// ---------------- per-graph top-k (full bitonic sort of 1024) -------------------
__global__ void topk_k(void* __restrict__ out, long long osz) {
    __shared__ unsigned long long keys[1024];
    const int b = blockIdx.x, t = threadIdx.x;
    float s = g_sval[b * Nn + t];
    unsigned u = __float_as_uint(s);
    u = (u & 0x80000000u) ? ~u : (u | 0x80000000u);
    u = ~u;
    keys[t] = ((unsigned long long)u << 32) | (unsigned)t;
    __syncthreads();
    for (int k = 2; k <= 1024; k <<= 1) {
        for (int j = k >> 1; j > 0; j >>= 1) {
            int ixj = t ^ j;
            if (ixj > t) {
                bool up = ((t & k) == 0);
                unsigned long long a = keys[t], bv = keys[ixj];
                if ((a > bv) == up) { keys[t] = bv; keys[ixj] = a; }
            }
            __syncthreads();
        }
    }
    g_nmap[b * Nn + t] = -1;
    __syncthreads();
    if (t < KPOOL) {
        int idx = (int)(keys[t] & 0xffffffffu);
        g_perm[b * KPOOL + t] = idx;
        g_vals[b * KPOOL + t] = g_sval[b * Nn + idx];
        g_nmap[b * Nn + idx] = t;
        st_out(out, OFF_PERM + b * KPOOL + t, (float)idx, osz);
    }
}

// ---------------- gated gather sub_x --------------------------------------------
__global__ void subx_k(void* __restrict__ out, long long osz) {
    long long idx = (long long)blockIdx.x * blockDim.x + threadIdx.x;
    int c = (int)(idx & 255);
    int r = (int)((idx >> 8) & 511);
    int b = (int)(idx >> 17);
    int p = g_perm[b * KPOOL + r];
    float v = g_q[((size_t)(b * Nn) + p) * HIDD + c] * g_vals[b * KPOOL + r];
    st_out(out, OFF_SUBX + idx, v, osz);
}

// ---------------- edge pipeline --------------------------------------------------
__global__ void zero_k() {
    int i = blockIdx.x * blockDim.x + threadIdx.x;
    if (i < Bb * BINS) g_cnt[i] = 0u;
}

__global__ void edge_k(const void* __restrict__ ei) {
    int e = blockIdx.x * blockDim.x + threadIdx.x;
    if (e >= Bb * EPER) return;
    int b = e >> 14;
    long long sv, dvv;
    if (g_is64) {
        const long long* p = (const long long*)ei;
        sv = p[e]; dvv = p[Bb * EPER + e];
    } else {
        const int* p = (const int*)ei;
        sv = p[e]; dvv = p[Bb * EPER + e];
    }
    int ls = (int)(sv - (long long)b * Nn);
    int ld = (int)(dvv - (long long)b * Nn);
    bool inr = (ls >= 0) && (ls < Nn) && (ld >= 0) && (ld < Nn);
    int nu = inr ? g_nmap[b * Nn + ls] : -1;
    int nv = inr ? g_nmap[b * Nn + ld] : -1;
    bool valid = (nu >= 0) && (nv >= 0);
    unsigned key = valid ? (unsigned)(nu * KPOOL + nv) : (unsigned)INVKEY;
    g_key[e] = key; g_nu[e] = nu; g_nv[e] = nv;
    atomicAdd(&g_cnt[(size_t)b * BINS + key], 1u);
}

__global__ void scan1_k() {
    __shared__ unsigned sh[1024];
    const int b = blockIdx.x, c = blockIdx.y, t = threadIdx.x;
    int i0 = c * CHUNK + t * 2;
    unsigned v0 = (i0     < BINS) ? g_cnt[(size_t)b * BINS + i0]     : 0u;
    unsigned v1 = (i0 + 1 < BINS) ? g_cnt[(size_t)b * BINS + i0 + 1] : 0u;
    sh[t] = v0 + v1;
    __syncthreads();
    for (int off = 1; off < 1024; off <<= 1) {
        unsigned x = (t >= off) ? sh[t - off] : 0u;
        __syncthreads();
        sh[t] += x;
        __syncthreads();
    }
    unsigned excl = t ? sh[t - 1] : 0u;
    if (i0     < BINS) g_scan[(size_t)b * BINS + i0]     = excl;
    if (i0 + 1 < BINS) g_scan[(size_t)b * BINS + i0 + 1] = excl + v0;
    if (t == 1023) g_chunk[b * NCH + c] = sh[1023];
}

__global__ void scan2_k() {
    int b = threadIdx.x;
    if (b >= Bb) return;
    unsigned run = 0;
    for (int c = 0; c < NCH; c++) {
        unsigned v = g_chunk[b * NCH + c];
        g_chunkEx[b * NCH + c] = run;
        run += v;
    }
}

// dynamic smem: [0,16384) keys, [16384,17408) scan
__global__ void scatter_k(void* __restrict__ out, long long osz) {
    extern __shared__ unsigned sdyn[];
    unsigned* skey = sdyn;
    unsigned* sh   = sdyn + EPER;
    const int b = blockIdx.x, t = threadIdx.x;
    const int gb = b * EPER;
#pragma unroll
    for (int u = 0; u < 16; u++) skey[u * 1024 + t] = g_key[gb + u * 1024 + t];
    __syncthreads();

    const int i0 = t * 16;
    unsigned cinv = 0;
#pragma unroll
    for (int u = 0; u < 16; u++) cinv += (skey[i0 + u] == (unsigned)INVKEY);
    sh[t] = cinv;
    __syncthreads();
    for (int off = 1; off < 1024; off <<= 1) {
        unsigned x = (t >= off) ? sh[t - off] : 0u;
        __syncthreads();
        sh[t] += x;
        __syncthreads();
    }
    unsigned invBase = t ? sh[t - 1] : 0u;
    unsigned nValid = g_scan[(size_t)b * BINS + INVKEY] + g_chunkEx[b * NCH + INVKEY / CHUNK];
    unsigned run = invBase;
    for (int u = 0; u < 16; u++) {
        int i = i0 + u;
        unsigned key = skey[i];
        bool valid = (key != (unsigned)INVKEY);
        unsigned pos;
        if (!valid) {
            pos = nValid + run; run++;
        } else {
            unsigned base = g_scan[(size_t)b * BINS + key] + g_chunkEx[b * NCH + key / CHUNK];
            unsigned cnt  = g_cnt[(size_t)b * BINS + key];
            unsigned rank = 0;
            if (cnt > 1) {   // rare collisions: stable within-bucket rank (smem scan)
                for (int j = 0; j < i; j++) rank += (skey[j] == key);
            }
            pos = base + rank;
        }
        int nu = g_nu[gb + i], nv = g_nv[gb + i];
        st_out(out, OFF_EDGE + (long long)(b * 2 + 0) * EPER + pos,
               valid ? (float)nu : -1.0f, osz);
        st_out(out, OFF_EDGE + (long long)(b * 2 + 1) * EPER + pos,
               valid ? (float)nv : -1.0f, osz);
        st_out(out, OFF_VALID + (long long)b * EPER + pos,
               valid ? 1.0f : 0.0f, osz);
    }
}

// ---------------- launch ---------------------------------------------------------
extern "C" void kernel_launch(void* const* d_in, const int* in_sizes, int n_in,
                              void* d_out, int out_size) {
    const float* x    = (const float*)d_in[0];
    const void*  ei   = d_in[1];
    const float* dist = (const float*)d_in[3];
    const float* Wq   = (const float*)d_in[5];
    const float* Wk   = (const float*)d_in[6];
    const float* Wv   = (const float*)d_in[7];
    const float* Wo   = (const float*)d_in[8];
    const float* tw   = (const float*)d_in[9];
    long long osz = (long long)out_size;

    detect_k<<<1, 1>>>((const int*)ei);

    dim3 gG(128, 4);
    sgemm_k<0,0><<<gG, 256>>>(x, Wq);          // Q -> g_q
    sgemm_k<1,1><<<gG, 256>>>(x, Wk);          // K -> g_kT [b,h,d,n]
    sgemm_k<1,2><<<gG, 256>>>(x, Wv);          // V -> g_vT [b,h,d,n]
    attn_k<<<dim3(64, 32), 256>>>(dist);       // -> g_att
    sgemm_k<0,3><<<gG, 256>>>(nullptr, Wo);    // g_att @ Wo -> g_q (encoder out)

    pack_k<<<2048, 1024>>>(d_out, osz);
    zero_k<<<2049, 1024>>>();
    score_k<<<1024, 256>>>(tw);
    topk_k<<<8, 1024>>>(d_out, osz);
    subx_k<<<4096, 256>>>(d_out, osz);
    edge_k<<<512, 256>>>(ei);
    scan1_k<<<dim3(8, 129), 1024>>>();
    scan2_k<<<1, 32>>>();

    const int scatter_smem = (EPER + 1024) * (int)sizeof(unsigned);
    cudaFuncSetAttribute(scatter_k, cudaFuncAttributeMaxDynamicSharedMemorySize,
                         scatter_smem);
    scatter_k<<<8, 1024, scatter_smem>>>(d_out, osz);
}

// round 4
// speedup vs baseline: 1.7006x; 1.0221x over previous
#include <cuda_runtime.h>
#include <math.h>
#include <stdint.h>

#define Bb 8
#define Nn 1024
#define HIDD 256
#define HEADS 8
#define DHH 32
#define KPOOL 512
#define EPER 16384
#define INVKEY (KPOOL*KPOOL)      // 262144
#define BINS (INVKEY+1)           // 262145
#define CHUNK 2048
#define NCH 129                   // ceil(BINS/CHUNK)

// ---------------- scratch (static device globals; no runtime alloc) -------------
__device__ float g_q  [Bb*Nn*HIDD];        // Q; later reused as encoder output
__device__ float g_kT [Bb*HEADS*DHH*Nn];   // [b,h,d,n]
__device__ float g_vT [Bb*HEADS*DHH*Nn];   // [b,h,d,n]
__device__ float g_att[Bb*Nn*HIDD];
__device__ float g_sval[Bb*Nn];
__device__ int   g_perm[Bb*KPOOL];
__device__ float g_vals[Bb*KPOOL];
__device__ int   g_nmap[Bb*Nn];
__device__ unsigned g_key[Bb*EPER];
__device__ int   g_nu[Bb*EPER];
__device__ int   g_nv[Bb*EPER];
__device__ unsigned g_cnt  [Bb*BINS];
__device__ unsigned g_scan [Bb*BINS];
__device__ unsigned g_chunk  [Bb*NCH];
__device__ unsigned g_chunkEx[Bb*NCH];
__device__ int   g_is64;

// output layout (elements, concatenated in reference return order)
#define OFF_ENC   ((long long)0)
#define OFF_SUBX  ((long long)2097152)
#define OFF_EDGE  ((long long)3145728)
#define OFF_PERM  ((long long)3407872)
#define OFF_VALID ((long long)3411968)

__device__ __forceinline__ void st_out(void* out, long long idx, float v,
                                       long long osz) {
    if (idx < 0 || idx >= osz) return;
    if (g_is64) ((double*)out)[idx] = (double)v;
    else        ((float*) out)[idx] = v;
}

// ---------------- input dtype probe ---------------------------------------------
__global__ void detect_k(const int* __restrict__ e32) {
    g_is64 = (e32[1] == 0 && e32[3] == 0 && e32[5] == 0 && e32[7] == 0) ? 1 : 0;
}

// ---------------- GEMM: C[M,256] = A[M,256] @ W[256,256] ------------------------
template<int MODE, int DST>
__global__ void sgemm_k(const float* __restrict__ A_in, const float* __restrict__ W) {
    const float* A = (A_in != nullptr) ? A_in : g_att;
    float* C = (DST == 1) ? g_kT : (DST == 2) ? g_vT : g_q;
    __shared__ float As[16][65];
    __shared__ float Ws[16][64];
    const int bm = blockIdx.x * 64, bn = blockIdx.y * 64;
    const int tid = threadIdx.x;
    const int tx = tid & 15, ty = tid >> 4;
    float acc[4][4];
#pragma unroll
    for (int i = 0; i < 4; i++)
#pragma unroll
        for (int j = 0; j < 4; j++) acc[i][j] = 0.f;

    for (int kk = 0; kk < HIDD; kk += 16) {
        {
            int m = tid >> 2, kq = tid & 3;
            float4 av = *(const float4*)&A[(size_t)(bm + m) * HIDD + kk + kq * 4];
            As[kq*4+0][m] = av.x; As[kq*4+1][m] = av.y;
            As[kq*4+2][m] = av.z; As[kq*4+3][m] = av.w;
        }
        {
            int k = tid >> 4, nq = tid & 15;
            *(float4*)&Ws[k][nq*4] =
                *(const float4*)&W[(size_t)(kk + k) * HIDD + bn + nq * 4];
        }
        __syncthreads();
#pragma unroll
        for (int k = 0; k < 16; k++) {
            float a0 = As[k][ty*4+0], a1 = As[k][ty*4+1];
            float a2 = As[k][ty*4+2], a3 = As[k][ty*4+3];
            float4 b4 = *(float4*)&Ws[k][tx*4];
            acc[0][0] += a0*b4.x; acc[0][1] += a0*b4.y; acc[0][2] += a0*b4.z; acc[0][3] += a0*b4.w;
            acc[1][0] += a1*b4.x; acc[1][1] += a1*b4.y; acc[1][2] += a1*b4.z; acc[1][3] += a1*b4.w;
            acc[2][0] += a2*b4.x; acc[2][1] += a2*b4.y; acc[2][2] += a2*b4.z; acc[2][3] += a2*b4.w;
            acc[3][0] += a3*b4.x; acc[3][1] += a3*b4.y; acc[3][2] += a3*b4.z; acc[3][3] += a3*b4.w;
        }
        __syncthreads();
    }
    if (MODE == 0) {
#pragma unroll
        for (int i = 0; i < 4; i++) {
            int row = bm + ty*4 + i;
            float4 v = make_float4(acc[i][0], acc[i][1], acc[i][2], acc[i][3]);
            *(float4*)&C[(size_t)row * HIDD + bn + tx*4] = v;
        }
    } else {
#pragma unroll
        for (int i = 0; i < 4; i++) {
            int row = bm + ty*4 + i;
            int b = row >> 10, n = row & 1023;
#pragma unroll
            for (int j = 0; j < 4; j++) {
                int col = bn + tx*4 + j;
                int h = col >> 5, d = col & 31;
                C[(size_t)(((b << 3) + h) * DHH + d) * Nn + n] = acc[i][j];
            }
        }
    }
}

// ---------------- flash attention (no-max softmax, pipelined KV) ----------------
__global__ void attn_k(const float* __restrict__ dist) {
    __shared__ float Qs[32][32];
    __shared__ float KT[32][132];
    __shared__ float VT[32][132];
    __shared__ float pbuf[8][4][128];
    const int bh = blockIdx.x;            // b*8+h
    const int b = bh >> 3, h = bh & 7;
    const int qbase = blockIdx.y * 32;
    const int tid = threadIdx.x, lane = tid & 31, warp = tid >> 5;
    const int r0 = warp * 4;
    const int Fd = tid >> 5;              // per-thread ldg mapping pieces
    const int Fk = tid & 31;

    {   // load Q tile [32 rows][32 dims]
        int rl = tid >> 3, dq = tid & 7;
        *(float4*)&Qs[rl][dq*4] =
            *(const float4*)&g_q[((size_t)(b * Nn) + (qbase + rl)) * HIDD + h * DHH + dq * 4];
    }

    // prefetch tile 0 K/V into regs
    float4 kreg[4], vreg[4];
#pragma unroll
    for (int i = 0; i < 4; i++) {
        int F = tid + i * 256;
        int d = F >> 5, kq = F & 31;
        size_t gidx = ((size_t)(bh * DHH) + d) * Nn + kq * 4;
        kreg[i] = *(const float4*)&g_kT[gidx];
        vreg[i] = *(const float4*)&g_vT[gidx];
    }
    float acc[4]   = {0.f, 0.f, 0.f, 0.f};
    float lpart[4] = {0.f, 0.f, 0.f, 0.f};
    __syncthreads();
#pragma unroll
    for (int i = 0; i < 4; i++) {
        int F = tid + i * 256;
        int d = F >> 5, kq = F & 31;
        *(float4*)&KT[d][kq*4] = kreg[i];
        *(float4*)&VT[d][kq*4] = vreg[i];
    }
    __syncthreads();

    const float isq = 0.17677669529663687f; // 1/sqrt(32)
    for (int kt = 0; kt < 8; kt++) {
        const int k0 = kt * 128;
        // prefetch next tile into regs (overlaps with compute below)
        if (kt < 7) {
#pragma unroll
            for (int i = 0; i < 4; i++) {
                int F = tid + i * 256;
                int d = F >> 5, kq = F & 31;
                size_t gidx = ((size_t)(bh * DHH) + d) * Nn + (k0 + 128) + kq * 4;
                kreg[i] = *(const float4*)&g_kT[gidx];
                vreg[i] = *(const float4*)&g_vT[gidx];
            }
        }
        // dist bias for this warp's 4 rows (issued early; L2-resident)
        float4 dv[4];
#pragma unroll
        for (int r = 0; r < 4; r++)
            dv[r] = *(const float4*)&dist[((size_t)(b * Nn + qbase + r0 + r)) * Nn + k0 + lane * 4];

        // QK: 4 rows per pass; Q via LDS.128 broadcast chunks
        float4 s[4];
#pragma unroll
        for (int r = 0; r < 4; r++) s[r] = make_float4(0.f, 0.f, 0.f, 0.f);
#pragma unroll
        for (int d4 = 0; d4 < 8; d4++) {
            float4 qv0 = *(float4*)&Qs[r0+0][d4*4];
            float4 qv1 = *(float4*)&Qs[r0+1][d4*4];
            float4 qv2 = *(float4*)&Qs[r0+2][d4*4];
            float4 qv3 = *(float4*)&Qs[r0+3][d4*4];
            const float* q0p = (const float*)&qv0;
            const float* q1p = (const float*)&qv1;
            const float* q2p = (const float*)&qv2;
            const float* q3p = (const float*)&qv3;
#pragma unroll
            for (int dd = 0; dd < 4; dd++) {
                float4 kv = *(float4*)&KT[d4*4+dd][lane*4];
                float q0 = q0p[dd], q1 = q1p[dd], q2 = q2p[dd], q3 = q3p[dd];
                s[0].x += q0*kv.x; s[0].y += q0*kv.y; s[0].z += q0*kv.z; s[0].w += q0*kv.w;
                s[1].x += q1*kv.x; s[1].y += q1*kv.y; s[1].z += q1*kv.z; s[1].w += q1*kv.w;
                s[2].x += q2*kv.x; s[2].y += q2*kv.y; s[2].z += q2*kv.z; s[2].w += q2*kv.w;
                s[3].x += q3*kv.x; s[3].y += q3*kv.y; s[3].z += q3*kv.z; s[3].w += q3*kv.w;
            }
        }

        // unnormalized exp (scores bounded; no max needed), per-lane l partial
#pragma unroll
        for (int r = 0; r < 4; r++) {
            float4 p4;
            p4.x = __expf(fmaf(s[r].x, isq, dv[r].x));
            p4.y = __expf(fmaf(s[r].y, isq, dv[r].y));
            p4.z = __expf(fmaf(s[r].z, isq, dv[r].z));
            p4.w = __expf(fmaf(s[r].w, isq, dv[r].w));
            lpart[r] += (p4.x + p4.y) + (p4.z + p4.w);
            *(float4*)&pbuf[warp][r][lane*4] = p4;
        }
        __syncwarp();

        // AV: all 4 rows in one pass over k (VT read once per warp)
#pragma unroll
        for (int k4 = 0; k4 < 32; k4++) {
            float4 vv = *(float4*)&VT[lane][k4*4];
            float4 p0 = *(float4*)&pbuf[warp][0][k4*4];
            float4 p1 = *(float4*)&pbuf[warp][1][k4*4];
            float4 p2 = *(float4*)&pbuf[warp][2][k4*4];
            float4 p3 = *(float4*)&pbuf[warp][3][k4*4];
            acc[0] += p0.x*vv.x + p0.y*vv.y + p0.z*vv.z + p0.w*vv.w;
            acc[1] += p1.x*vv.x + p1.y*vv.y + p1.z*vv.z + p1.w*vv.w;
            acc[2] += p2.x*vv.x + p2.y*vv.y + p2.z*vv.z + p2.w*vv.w;
            acc[3] += p3.x*vv.x + p3.y*vv.y + p3.z*vv.z + p3.w*vv.w;
        }
        __syncwarp();

        // stage next tile into smem
        if (kt < 7) {
            __syncthreads();
#pragma unroll
            for (int i = 0; i < 4; i++) {
                int F = tid + i * 256;
                int d = F >> 5, kq = F & 31;
                *(float4*)&KT[d][kq*4] = kreg[i];
                *(float4*)&VT[d][kq*4] = vreg[i];
            }
            __syncthreads();
        }
    }
    (void)Fd; (void)Fk;
    // final: reduce l across lanes once per row, normalize, store
#pragma unroll
    for (int r = 0; r < 4; r++) {
        float l = lpart[r];
#pragma unroll
        for (int o = 16; o; o >>= 1) l += __shfl_xor_sync(0xffffffffu, l, o);
        int row = qbase + r0 + r;
        g_att[((size_t)(b * Nn) + row) * HIDD + h * DHH + lane] = acc[r] / l;
    }
}

// ---------------- pack encoder result to output ---------------------------------
__global__ void pack_k(void* __restrict__ out, long long osz) {
    long long i = (long long)blockIdx.x * blockDim.x + threadIdx.x;
    if (i < (long long)Bb * Nn * HIDD) st_out(out, OFF_ENC + i, g_q[i], osz);
}

// ---------------- tanh projection scores ---------------------------------------
__global__ void score_k(const float* __restrict__ w) {
    int gw = (blockIdx.x * blockDim.x + threadIdx.x) >> 5;
    int lane = threadIdx.x & 31;
    if (gw >= Bb * Nn) return;
    float nw = 0.f, dot = 0.f;
#pragma unroll
    for (int i = 0; i < 8; i++) {
        float wv = w[lane + i * 32];
        nw += wv * wv;
        dot += wv * g_q[(size_t)gw * HIDD + lane + i * 32];
    }
#pragma unroll
    for (int o = 16; o; o >>= 1) {
        nw  += __shfl_xor_sync(0xffffffffu, nw, o);
        dot += __shfl_xor_sync(0xffffffffu, dot, o);
    }
    if (lane == 0) g_sval[gw] = tanhf(dot / sqrtf(nw));
}

// ---------------- per-graph top-k (full bitonic sort of 1024) -------------------
__global__ void topk_k(void* __restrict__ out, long long osz) {
    __shared__ unsigned long long keys[1024];
    const int b = blockIdx.x, t = threadIdx.x;
    float s = g_sval[b * Nn + t];
    unsigned u = __float_as_uint(s);
    u = (u & 0x80000000u) ? ~u : (u | 0x80000000u);
    u = ~u;
    keys[t] = ((unsigned long long)u << 32) | (unsigned)t;
    __syncthreads();
    for (int k = 2; k <= 1024; k <<= 1) {
        for (int j = k >> 1; j > 0; j >>= 1) {
            int ixj = t ^ j;
            if (ixj > t) {
                bool up = ((t & k) == 0);
                unsigned long long a = keys[t], bv = keys[ixj];
                if ((a > bv) == up) { keys[t] = bv; keys[ixj] = a; }
            }
            __syncthreads();
        }
    }
    g_nmap[b * Nn + t] = -1;
    __syncthreads();
    if (t < KPOOL) {
        int idx = (int)(keys[t] & 0xffffffffu);
        g_perm[b * KPOOL + t] = idx;
        g_vals[b * KPOOL + t] = g_sval[b * Nn + idx];
        g_nmap[b * Nn + idx] = t;
        st_out(out, OFF_PERM + b * KPOOL + t, (float)idx, osz);
    }
}

// ---------------- gated gather sub_x --------------------------------------------
__global__ void subx_k(void* __restrict__ out, long long osz) {
    long long idx = (long long)blockIdx.x * blockDim.x + threadIdx.x;
    int c = (int)(idx & 255);
    int r = (int)((idx >> 8) & 511);
    int b = (int)(idx >> 17);
    int p = g_perm[b * KPOOL + r];
    float v = g_q[((size_t)(b * Nn) + p) * HIDD + c] * g_vals[b * KPOOL + r];
    st_out(out, OFF_SUBX + idx, v, osz);
}

// ---------------- edge pipeline --------------------------------------------------
__global__ void zero_k() {
    int i = blockIdx.x * blockDim.x + threadIdx.x;
    if (i < Bb * BINS) g_cnt[i] = 0u;
}

__global__ void edge_k(const void* __restrict__ ei) {
    int e = blockIdx.x * blockDim.x + threadIdx.x;
    if (e >= Bb * EPER) return;
    int b = e >> 14;
    long long sv, dvv;
    if (g_is64) {
        const long long* p = (const long long*)ei;
        sv = p[e]; dvv = p[Bb * EPER + e];
    } else {
        const int* p = (const int*)ei;
        sv = p[e]; dvv = p[Bb * EPER + e];
    }
    int ls = (int)(sv - (long long)b * Nn);
    int ld = (int)(dvv - (long long)b * Nn);
    bool inr = (ls >= 0) && (ls < Nn) && (ld >= 0) && (ld < Nn);
    int nu = inr ? g_nmap[b * Nn + ls] : -1;
    int nv = inr ? g_nmap[b * Nn + ld] : -1;
    bool valid = (nu >= 0) && (nv >= 0);
    unsigned key = valid ? (unsigned)(nu * KPOOL + nv) : (unsigned)INVKEY;
    g_key[e] = key; g_nu[e] = nu; g_nv[e] = nv;
    atomicAdd(&g_cnt[(size_t)b * BINS + key], 1u);
}

__global__ void scan1_k() {
    __shared__ unsigned sh[1024];
    const int b = blockIdx.x, c = blockIdx.y, t = threadIdx.x;
    int i0 = c * CHUNK + t * 2;
    unsigned v0 = (i0     < BINS) ? g_cnt[(size_t)b * BINS + i0]     : 0u;
    unsigned v1 = (i0 + 1 < BINS) ? g_cnt[(size_t)b * BINS + i0 + 1] : 0u;
    sh[t] = v0 + v1;
    __syncthreads();
    for (int off = 1; off < 1024; off <<= 1) {
        unsigned x = (t >= off) ? sh[t - off] : 0u;
        __syncthreads();
        sh[t] += x;
        __syncthreads();
    }
    unsigned excl = t ? sh[t - 1] : 0u;
    if (i0     < BINS) g_scan[(size_t)b * BINS + i0]     = excl;
    if (i0 + 1 < BINS) g_scan[(size_t)b * BINS + i0 + 1] = excl + v0;
    if (t == 1023) g_chunk[b * NCH + c] = sh[1023];
}

__global__ void scan2_k() {
    int b = threadIdx.x;
    if (b >= Bb) return;
    unsigned run = 0;
    for (int c = 0; c < NCH; c++) {
        unsigned v = g_chunk[b * NCH + c];
        g_chunkEx[b * NCH + c] = run;
        run += v;
    }
}

// dynamic smem: [0,16384) keys, [16384,17408) scan
__global__ void scatter_k(void* __restrict__ out, long long osz) {
    extern __shared__ unsigned sdyn[];
    unsigned* skey = sdyn;
    unsigned* sh   = sdyn + EPER;
    const int b = blockIdx.x, t = threadIdx.x;
    const int gb = b * EPER;
#pragma unroll
    for (int u = 0; u < 16; u++) skey[u * 1024 + t] = g_key[gb + u * 1024 + t];
    __syncthreads();

    const int i0 = t * 16;
    unsigned cinv = 0;
#pragma unroll
    for (int u = 0; u < 16; u++) cinv += (skey[i0 + u] == (unsigned)INVKEY);
    sh[t] = cinv;
    __syncthreads();
    for (int off = 1; off < 1024; off <<= 1) {
        unsigned x = (t >= off) ? sh[t - off] : 0u;
        __syncthreads();
        sh[t] += x;
        __syncthreads();
    }
    unsigned invBase = t ? sh[t - 1] : 0u;
    unsigned nValid = g_scan[(size_t)b * BINS + INVKEY] + g_chunkEx[b * NCH + INVKEY / CHUNK];
    unsigned run = invBase;
    for (int u = 0; u < 16; u++) {
        int i = i0 + u;
        unsigned key = skey[i];
        bool valid = (key != (unsigned)INVKEY);
        unsigned pos;
        if (!valid) {
            pos = nValid + run; run++;
        } else {
            unsigned base = g_scan[(size_t)b * BINS + key] + g_chunkEx[b * NCH + key / CHUNK];
            unsigned cnt  = g_cnt[(size_t)b * BINS + key];
            unsigned rank = 0;
            if (cnt > 1) {   // rare collisions: stable within-bucket rank (smem scan)
                for (int j = 0; j < i; j++) rank += (skey[j] == key);
            }
            pos = base + rank;
        }
        int nu = g_nu[gb + i], nv = g_nv[gb + i];
        st_out(out, OFF_EDGE + (long long)(b * 2 + 0) * EPER + pos,
               valid ? (float)nu : -1.0f, osz);
        st_out(out, OFF_EDGE + (long long)(b * 2 + 1) * EPER + pos,
               valid ? (float)nv : -1.0f, osz);
        st_out(out, OFF_VALID + (long long)b * EPER + pos,
               valid ? 1.0f : 0.0f, osz);
    }
}

// ---------------- launch ---------------------------------------------------------
extern "C" void kernel_launch(void* const* d_in, const int* in_sizes, int n_in,
                              void* d_out, int out_size) {
    const float* x    = (const float*)d_in[0];
    const void*  ei   = d_in[1];
    const float* dist = (const float*)d_in[3];
    const float* Wq   = (const float*)d_in[5];
    const float* Wk   = (const float*)d_in[6];
    const float* Wv   = (const float*)d_in[7];
    const float* Wo   = (const float*)d_in[8];
    const float* tw   = (const float*)d_in[9];
    long long osz = (long long)out_size;

    detect_k<<<1, 1>>>((const int*)ei);

    dim3 gG(128, 4);
    sgemm_k<0,0><<<gG, 256>>>(x, Wq);          // Q -> g_q
    sgemm_k<1,1><<<gG, 256>>>(x, Wk);          // K -> g_kT [b,h,d,n]
    sgemm_k<1,2><<<gG, 256>>>(x, Wv);          // V -> g_vT [b,h,d,n]
    attn_k<<<dim3(64, 32), 256>>>(dist);       // -> g_att
    sgemm_k<0,3><<<gG, 256>>>(nullptr, Wo);    // g_att @ Wo -> g_q (encoder out)

    pack_k<<<2048, 1024>>>(d_out, osz);
    zero_k<<<2049, 1024>>>();
    score_k<<<1024, 256>>>(tw);
    topk_k<<<8, 1024>>>(d_out, osz);
    subx_k<<<4096, 256>>>(d_out, osz);
    edge_k<<<512, 256>>>(ei);
    scan1_k<<<dim3(8, 129), 1024>>>();
    scan2_k<<<1, 32>>>();

    const int scatter_smem = (EPER + 1024) * (int)sizeof(unsigned);
    cudaFuncSetAttribute(scatter_k, cudaFuncAttributeMaxDynamicSharedMemorySize,
                         scatter_smem);
    scatter_k<<<8, 1024, scatter_smem>>>(d_out, osz);
}

// round 7
// speedup vs baseline: 1.7081x; 1.0044x over previous
#include <cuda_runtime.h>
#include <math.h>
#include <stdint.h>

#define Bb 8
#define Nn 1024
#define HIDD 256
#define HEADS 8
#define DHH 32
#define KPOOL 512
#define EPER 16384
#define INVKEY (KPOOL*KPOOL)      // 262144
#define BINS (INVKEY+1)           // 262145
#define CHUNK 2048
#define NCH 129                   // ceil(BINS/CHUNK)

// ---------------- scratch (static device globals; no runtime alloc) -------------
__device__ float g_q  [Bb*Nn*HIDD];        // Q; later reused as encoder output
__device__ float g_kT [Bb*HEADS*DHH*Nn];   // [b,h,d,n]
__device__ float g_vT [Bb*HEADS*DHH*Nn];   // [b,h,d,n]
__device__ float g_att[Bb*Nn*HIDD];
__device__ float g_sval[Bb*Nn];
__device__ int   g_perm[Bb*KPOOL];
__device__ float g_vals[Bb*KPOOL];
__device__ int   g_nmap[Bb*Nn];
__device__ unsigned g_key[Bb*EPER];
__device__ int   g_nu[Bb*EPER];
__device__ int   g_nv[Bb*EPER];
__device__ unsigned g_cnt  [Bb*BINS];
__device__ unsigned g_scan [Bb*BINS];
__device__ unsigned g_chunk  [Bb*NCH];
__device__ unsigned g_chunkEx[Bb*NCH];
__device__ int   g_is64;

// output layout (elements, concatenated in reference return order)
#define OFF_ENC   ((long long)0)
#define OFF_SUBX  ((long long)2097152)
#define OFF_EDGE  ((long long)3145728)
#define OFF_PERM  ((long long)3407872)
#define OFF_VALID ((long long)3411968)

__device__ __forceinline__ void st_out(void* out, long long idx, float v,
                                       long long osz) {
    if (idx < 0 || idx >= osz) return;
    if (g_is64) ((double*)out)[idx] = (double)v;
    else        ((float*) out)[idx] = v;
}

__device__ __forceinline__ void cpa16(uint32_t dst, const void* src) {
    asm volatile("cp.async.cg.shared.global [%0], [%1], 16;\n"
                 :: "r"(dst), "l"(src));
}

// ---------------- input dtype probe ---------------------------------------------
__global__ void detect_k(const int* __restrict__ e32) {
    g_is64 = (e32[1] == 0 && e32[3] == 0 && e32[5] == 0 && e32[7] == 0) ? 1 : 0;
}

// ---------------- GEMM: C[M,256] = A[M,256] @ W[256,256] ------------------------
// MODE 0: row-major store.  MODE 1: store transposed to [b,h,d,n].
// DST: 0=g_q  1=g_kT  2=g_vT  3=g_q + packed copy to out (encoder result).
template<int MODE, int DST>
__global__ void sgemm_k(const float* __restrict__ A_in, const float* __restrict__ W,
                        void* __restrict__ out, long long osz) {
    const float* A = (A_in != nullptr) ? A_in : g_att;
    float* C = (DST == 1) ? g_kT : (DST == 2) ? g_vT : g_q;
    __shared__ float As[16][65];
    __shared__ float Ws[16][64];
    const int bm = blockIdx.x * 64, bn = blockIdx.y * 64;
    const int tid = threadIdx.x;
    const int tx = tid & 15, ty = tid >> 4;
    float acc[4][4];
#pragma unroll
    for (int i = 0; i < 4; i++)
#pragma unroll
        for (int j = 0; j < 4; j++) acc[i][j] = 0.f;

    for (int kk = 0; kk < HIDD; kk += 16) {
        {
            int m = tid >> 2, kq = tid & 3;
            float4 av = *(const float4*)&A[(size_t)(bm + m) * HIDD + kk + kq * 4];
            As[kq*4+0][m] = av.x; As[kq*4+1][m] = av.y;
            As[kq*4+2][m] = av.z; As[kq*4+3][m] = av.w;
        }
        {
            int k = tid >> 4, nq = tid & 15;
            *(float4*)&Ws[k][nq*4] =
                *(const float4*)&W[(size_t)(kk + k) * HIDD + bn + nq * 4];
        }
        __syncthreads();
#pragma unroll
        for (int k = 0; k < 16; k++) {
            float a0 = As[k][ty*4+0], a1 = As[k][ty*4+1];
            float a2 = As[k][ty*4+2], a3 = As[k][ty*4+3];
            float4 b4 = *(float4*)&Ws[k][tx*4];
            acc[0][0] += a0*b4.x; acc[0][1] += a0*b4.y; acc[0][2] += a0*b4.z; acc[0][3] += a0*b4.w;
            acc[1][0] += a1*b4.x; acc[1][1] += a1*b4.y; acc[1][2] += a1*b4.z; acc[1][3] += a1*b4.w;
            acc[2][0] += a2*b4.x; acc[2][1] += a2*b4.y; acc[2][2] += a2*b4.z; acc[2][3] += a2*b4.w;
            acc[3][0] += a3*b4.x; acc[3][1] += a3*b4.y; acc[3][2] += a3*b4.z; acc[3][3] += a3*b4.w;
        }
        __syncthreads();
    }
    if (MODE == 0) {
#pragma unroll
        for (int i = 0; i < 4; i++) {
            int row = bm + ty*4 + i;
            float4 v = make_float4(acc[i][0], acc[i][1], acc[i][2], acc[i][3]);
            *(float4*)&C[(size_t)row * HIDD + bn + tx*4] = v;
            if (DST == 3) {
                long long base = (long long)row * HIDD + bn + tx*4;
#pragma unroll
                for (int j = 0; j < 4; j++)
                    st_out(out, OFF_ENC + base + j, acc[i][j], osz);
            }
        }
    } else {
#pragma unroll
        for (int i = 0; i < 4; i++) {
            int row = bm + ty*4 + i;
            int b = row >> 10, n = row & 1023;
#pragma unroll
            for (int j = 0; j < 4; j++) {
                int col = bn + tx*4 + j;
                int h = col >> 5, d = col & 31;
                C[(size_t)(((b << 3) + h) * DHH + d) * Nn + n] = acc[i][j];
            }
        }
    }
}

// ---------------- flash attention -----------------------------------------------
// Loads: cp.async double-buffered (occupancy fix). Compute: verbatim round-4
// arithmetic (bit-identical results -> identical topk selection).
#define KVP 132
__global__ void attn_k(const float* __restrict__ dist) {
    extern __shared__ float sm[];
    float* Qs   = sm;                 // [32][32]
    float* KTb0 = sm + 1024;          // [32][KVP]
    float* KTb1 = KTb0 + 32*KVP;
    float* VTb0 = KTb1 + 32*KVP;
    float* VTb1 = VTb0 + 32*KVP;
    float* pb   = VTb1 + 32*KVP;      // [8][4][128]
    const int bh = blockIdx.x;            // b*8+h
    const int b = bh >> 3, h = bh & 7;
    const int qbase = blockIdx.y * 32;
    const int tid = threadIdx.x, lane = tid & 31, warp = tid >> 5;
    const int r0 = warp * 4;
    const int cd = tid >> 5;              // d-slice base for loads
    const int ck = (tid & 31) * 4;        // k offset (floats)

    // issue tile-0 K/V loads (async, no register transit)
    {
#pragma unroll
        for (int i = 0; i < 4; i++) {
            int d = cd + i * 8;
            size_t goff = ((size_t)(bh * DHH) + d) * Nn + ck;
            cpa16((uint32_t)__cvta_generic_to_shared(KTb0 + d*KVP + ck), &g_kT[goff]);
            cpa16((uint32_t)__cvta_generic_to_shared(VTb0 + d*KVP + ck), &g_vT[goff]);
        }
        asm volatile("cp.async.commit_group;\n" ::: "memory");
    }
    {   // load Q tile [32 rows][32 dims]
        int rl = tid >> 3, dq = tid & 7;
        *(float4*)&Qs[rl*32 + dq*4] =
            *(const float4*)&g_q[((size_t)(b * Nn) + (qbase + rl)) * HIDD + h * DHH + dq * 4];
    }

    float acc[4]   = {0.f, 0.f, 0.f, 0.f};
    float lpart[4] = {0.f, 0.f, 0.f, 0.f};
    const float isq = 0.17677669529663687f; // 1/sqrt(32)

    for (int kt = 0; kt < 8; kt++) {
        const int k0 = kt * 128;
        float* KTc = (kt & 1) ? KTb1 : KTb0;
        float* VTc = (kt & 1) ? VTb1 : VTb0;
        __syncthreads();   // prior compute done on buffer we are about to fill
        if (kt < 7) {
            float* KTn = (kt & 1) ? KTb0 : KTb1;
            float* VTn = (kt & 1) ? VTb0 : VTb1;
#pragma unroll
            for (int i = 0; i < 4; i++) {
                int d = cd + i * 8;
                size_t goff = ((size_t)(bh * DHH) + d) * Nn + (k0 + 128) + ck;
                cpa16((uint32_t)__cvta_generic_to_shared(KTn + d*KVP + ck), &g_kT[goff]);
                cpa16((uint32_t)__cvta_generic_to_shared(VTn + d*KVP + ck), &g_vT[goff]);
            }
            asm volatile("cp.async.commit_group;\n" ::: "memory");
            asm volatile("cp.async.wait_group 1;\n" ::: "memory");
        } else {
            asm volatile("cp.async.wait_group 0;\n" ::: "memory");
        }
        __syncthreads();   // tile kt visible

        // ---- compute below is verbatim round-4 arithmetic ----
        float4 dv[4];
#pragma unroll
        for (int r = 0; r < 4; r++)
            dv[r] = *(const float4*)&dist[((size_t)(b * Nn + qbase + r0 + r)) * Nn + k0 + lane * 4];

        float4 s[4];
#pragma unroll
        for (int r = 0; r < 4; r++) s[r] = make_float4(0.f, 0.f, 0.f, 0.f);
#pragma unroll
        for (int d4 = 0; d4 < 8; d4++) {
            float4 qv0 = *(float4*)&Qs[(r0+0)*32 + d4*4];
            float4 qv1 = *(float4*)&Qs[(r0+1)*32 + d4*4];
            float4 qv2 = *(float4*)&Qs[(r0+2)*32 + d4*4];
            float4 qv3 = *(float4*)&Qs[(r0+3)*32 + d4*4];
            const float* q0p = (const float*)&qv0;
            const float* q1p = (const float*)&qv1;
            const float* q2p = (const float*)&qv2;
            const float* q3p = (const float*)&qv3;
#pragma unroll
            for (int dd = 0; dd < 4; dd++) {
                float4 kv = *(float4*)&KTc[(d4*4+dd)*KVP + lane*4];
                float q0 = q0p[dd], q1 = q1p[dd], q2 = q2p[dd], q3 = q3p[dd];
                s[0].x += q0*kv.x; s[0].y += q0*kv.y; s[0].z += q0*kv.z; s[0].w += q0*kv.w;
                s[1].x += q1*kv.x; s[1].y += q1*kv.y; s[1].z += q1*kv.z; s[1].w += q1*kv.w;
                s[2].x += q2*kv.x; s[2].y += q2*kv.y; s[2].z += q2*kv.z; s[2].w += q2*kv.w;
                s[3].x += q3*kv.x; s[3].y += q3*kv.y; s[3].z += q3*kv.z; s[3].w += q3*kv.w;
            }
        }

#pragma unroll
        for (int r = 0; r < 4; r++) {
            float4 p4;
            p4.x = __expf(fmaf(s[r].x, isq, dv[r].x));
            p4.y = __expf(fmaf(s[r].y, isq, dv[r].y));
            p4.z = __expf(fmaf(s[r].z, isq, dv[r].z));
            p4.w = __expf(fmaf(s[r].w, isq, dv[r].w));
            lpart[r] += (p4.x + p4.y) + (p4.z + p4.w);
            *(float4*)&pb[(warp*4 + r)*128 + lane*4] = p4;
        }
        __syncwarp();

#pragma unroll
        for (int k4 = 0; k4 < 32; k4++) {
            float4 vv = *(float4*)&VTc[lane*KVP + k4*4];
            float4 p0 = *(float4*)&pb[(warp*4+0)*128 + k4*4];
            float4 p1 = *(float4*)&pb[(warp*4+1)*128 + k4*4];
            float4 p2 = *(float4*)&pb[(warp*4+2)*128 + k4*4];
            float4 p3 = *(float4*)&pb[(warp*4+3)*128 + k4*4];
            acc[0] += p0.x*vv.x + p0.y*vv.y + p0.z*vv.z + p0.w*vv.w;
            acc[1] += p1.x*vv.x + p1.y*vv.y + p1.z*vv.z + p1.w*vv.w;
            acc[2] += p2.x*vv.x + p2.y*vv.y + p2.z*vv.z + p2.w*vv.w;
            acc[3] += p3.x*vv.x + p3.y*vv.y + p3.z*vv.z + p3.w*vv.w;
        }
        __syncwarp();
    }
    // final: reduce l across lanes once per row, normalize, store
#pragma unroll
    for (int r = 0; r < 4; r++) {
        float l = lpart[r];
#pragma unroll
        for (int o = 16; o; o >>= 1) l += __shfl_xor_sync(0xffffffffu, l, o);
        int row = qbase + r0 + r;
        g_att[((size_t)(b * Nn) + row) * HIDD + h * DHH + lane] = acc[r] / l;
    }
}
#define ATTN_SMEM ((1024 + 4*32*KVP + 8*4*128) * (int)sizeof(float))

// ---------------- tanh projection scores ---------------------------------------
__global__ void score_k(const float* __restrict__ w) {
    int gw = (blockIdx.x * blockDim.x + threadIdx.x) >> 5;
    int lane = threadIdx.x & 31;
    if (gw >= Bb * Nn) return;
    float nw = 0.f, dot = 0.f;
#pragma unroll
    for (int i = 0; i < 8; i++) {
        float wv = w[lane + i * 32];
        nw += wv * wv;
        dot += wv * g_q[(size_t)gw * HIDD + lane + i * 32];
    }
#pragma unroll
    for (int o = 16; o; o >>= 1) {
        nw  += __shfl_xor_sync(0xffffffffu, nw, o);
        dot += __shfl_xor_sync(0xffffffffu, dot, o);
    }
    if (lane == 0) g_sval[gw] = tanhf(dot / sqrtf(nw));
}

// ---------------- per-graph top-k (full bitonic sort of 1024) -------------------
__global__ void topk_k(void* __restrict__ out, long long osz) {
    __shared__ unsigned long long keys[1024];
    const int b = blockIdx.x, t = threadIdx.x;
    float s = g_sval[b * Nn + t];
    unsigned u = __float_as_uint(s);
    u = (u & 0x80000000u) ? ~u : (u | 0x80000000u);
    u = ~u;
    keys[t] = ((unsigned long long)u << 32) | (unsigned)t;
    __syncthreads();
    for (int k = 2; k <= 1024; k <<= 1) {
        for (int j = k >> 1; j > 0; j >>= 1) {
            int ixj = t ^ j;
            if (ixj > t) {
                bool up = ((t & k) == 0);
                unsigned long long a = keys[t], bv = keys[ixj];
                if ((a > bv) == up) { keys[t] = bv; keys[ixj] = a; }
            }
            __syncthreads();
        }
    }
    g_nmap[b * Nn + t] = -1;
    __syncthreads();
    if (t < KPOOL) {
        int idx = (int)(keys[t] & 0xffffffffu);
        g_perm[b * KPOOL + t] = idx;
        g_vals[b * KPOOL + t] = g_sval[b * Nn + idx];
        g_nmap[b * Nn + idx] = t;
        st_out(out, OFF_PERM + b * KPOOL + t, (float)idx, osz);
    }
}

// ---------------- gated gather sub_x --------------------------------------------
__global__ void subx_k(void* __restrict__ out, long long osz) {
    long long idx = (long long)blockIdx.x * blockDim.x + threadIdx.x;
    int c = (int)(idx & 255);
    int r = (int)((idx >> 8) & 511);
    int b = (int)(idx >> 17);
    int p = g_perm[b * KPOOL + r];
    float v = g_q[((size_t)(b * Nn) + p) * HIDD + c] * g_vals[b * KPOOL + r];
    st_out(out, OFF_SUBX + idx, v, osz);
}

// ---------------- edge pipeline --------------------------------------------------
__global__ void zero_k() {
    int i = blockIdx.x * blockDim.x + threadIdx.x;
    if (i < Bb * BINS) g_cnt[i] = 0u;
}

__global__ void edge_k(const void* __restrict__ ei) {
    int e = blockIdx.x * blockDim.x + threadIdx.x;
    if (e >= Bb * EPER) return;
    int b = e >> 14;
    long long sv, dvv;
    if (g_is64) {
        const long long* p = (const long long*)ei;
        sv = p[e]; dvv = p[Bb * EPER + e];
    } else {
        const int* p = (const int*)ei;
        sv = p[e]; dvv = p[Bb * EPER + e];
    }
    int ls = (int)(sv - (long long)b * Nn);
    int ld = (int)(dvv - (long long)b * Nn);
    bool inr = (ls >= 0) && (ls < Nn) && (ld >= 0) && (ld < Nn);
    int nu = inr ? g_nmap[b * Nn + ls] : -1;
    int nv = inr ? g_nmap[b * Nn + ld] : -1;
    bool valid = (nu >= 0) && (nv >= 0);
    unsigned key = valid ? (unsigned)(nu * KPOOL + nv) : (unsigned)INVKEY;
    g_key[e] = key; g_nu[e] = nu; g_nv[e] = nv;
    atomicAdd(&g_cnt[(size_t)b * BINS + key], 1u);
}

__global__ void scan1_k() {
    __shared__ unsigned sh[1024];
    const int b = blockIdx.x, c = blockIdx.y, t = threadIdx.x;
    int i0 = c * CHUNK + t * 2;
    unsigned v0 = (i0     < BINS) ? g_cnt[(size_t)b * BINS + i0]     : 0u;
    unsigned v1 = (i0 + 1 < BINS) ? g_cnt[(size_t)b * BINS + i0 + 1] : 0u;
    sh[t] = v0 + v1;
    __syncthreads();
    for (int off = 1; off < 1024; off <<= 1) {
        unsigned x = (t >= off) ? sh[t - off] : 0u;
        __syncthreads();
        sh[t] += x;
        __syncthreads();
    }
    unsigned excl = t ? sh[t - 1] : 0u;
    if (i0     < BINS) g_scan[(size_t)b * BINS + i0]     = excl;
    if (i0 + 1 < BINS) g_scan[(size_t)b * BINS + i0 + 1] = excl + v0;
    if (t == 1023) g_chunk[b * NCH + c] = sh[1023];
}

__global__ void scan2_k() {
    int b = threadIdx.x;
    if (b >= Bb) return;
    unsigned run = 0;
    for (int c = 0; c < NCH; c++) {
        unsigned v = g_chunk[b * NCH + c];
        g_chunkEx[b * NCH + c] = run;
        run += v;
    }
}

// dynamic smem: [0,16384) keys, [16384,17408) scan
__global__ void scatter_k(void* __restrict__ out, long long osz) {
    extern __shared__ unsigned sdyn[];
    unsigned* skey = sdyn;
    unsigned* sh   = sdyn + EPER;
    const int b = blockIdx.x, t = threadIdx.x;
    const int gb = b * EPER;
#pragma unroll
    for (int u = 0; u < 16; u++) skey[u * 1024 + t] = g_key[gb + u * 1024 + t];
    __syncthreads();

    const int i0 = t * 16;
    unsigned cinv = 0;
#pragma unroll
    for (int u = 0; u < 16; u++) cinv += (skey[i0 + u] == (unsigned)INVKEY);
    sh[t] = cinv;
    __syncthreads();
    for (int off = 1; off < 1024; off <<= 1) {
        unsigned x = (t >= off) ? sh[t - off] : 0u;
        __syncthreads();
        sh[t] += x;
        __syncthreads();
    }
    unsigned invBase = t ? sh[t - 1] : 0u;
    unsigned nValid = g_scan[(size_t)b * BINS + INVKEY] + g_chunkEx[b * NCH + INVKEY / CHUNK];
    unsigned run = invBase;
    for (int u = 0; u < 16; u++) {
        int i = i0 + u;
        unsigned key = skey[i];
        bool valid = (key != (unsigned)INVKEY);
        unsigned pos;
        if (!valid) {
            pos = nValid + run; run++;
        } else {
            unsigned base = g_scan[(size_t)b * BINS + key] + g_chunkEx[b * NCH + key / CHUNK];
            unsigned cnt  = g_cnt[(size_t)b * BINS + key];
            unsigned rank = 0;
            if (cnt > 1) {   // rare collisions: stable within-bucket rank (smem scan)
                for (int j = 0; j < i; j++) rank += (skey[j] == key);
            }
            pos = base + rank;
        }
        int nu = g_nu[gb + i], nv = g_nv[gb + i];
        st_out(out, OFF_EDGE + (long long)(b * 2 + 0) * EPER + pos,
               valid ? (float)nu : -1.0f, osz);
        st_out(out, OFF_EDGE + (long long)(b * 2 + 1) * EPER + pos,
               valid ? (float)nv : -1.0f, osz);
        st_out(out, OFF_VALID + (long long)b * EPER + pos,
               valid ? 1.0f : 0.0f, osz);
    }
}

// ---------------- launch ---------------------------------------------------------
extern "C" void kernel_launch(void* const* d_in, const int* in_sizes, int n_in,
                              void* d_out, int out_size) {
    const float* x    = (const float*)d_in[0];
    const void*  ei   = d_in[1];
    const float* dist = (const float*)d_in[3];
    const float* Wq   = (const float*)d_in[5];
    const float* Wk   = (const float*)d_in[6];
    const float* Wv   = (const float*)d_in[7];
    const float* Wo   = (const float*)d_in[8];
    const float* tw   = (const float*)d_in[9];
    long long osz = (long long)out_size;

    detect_k<<<1, 1>>>((const int*)ei);

    dim3 gG(128, 4);
    sgemm_k<0,0><<<gG, 256>>>(x, Wq, nullptr, 0);   // Q -> g_q
    sgemm_k<1,1><<<gG, 256>>>(x, Wk, nullptr, 0);   // K -> g_kT [b,h,d,n]
    sgemm_k<1,2><<<gG, 256>>>(x, Wv, nullptr, 0);   // V -> g_vT [b,h,d,n]

    cudaFuncSetAttribute(attn_k, cudaFuncAttributeMaxDynamicSharedMemorySize,
                         ATTN_SMEM);
    attn_k<<<dim3(64, 32), 256, ATTN_SMEM>>>(dist); // -> g_att

    sgemm_k<0,3><<<gG, 256>>>(nullptr, Wo, d_out, osz); // -> g_q + out (fused pack)

    zero_k<<<2049, 1024>>>();
    score_k<<<1024, 256>>>(tw);
    topk_k<<<8, 1024>>>(d_out, osz);
    subx_k<<<4096, 256>>>(d_out, osz);
    edge_k<<<512, 256>>>(ei);
    scan1_k<<<dim3(8, 129), 1024>>>();
    scan2_k<<<1, 32>>>();

    const int scatter_smem = (EPER + 1024) * (int)sizeof(unsigned);
    cudaFuncSetAttribute(scatter_k, cudaFuncAttributeMaxDynamicSharedMemorySize,
                         scatter_smem);
    scatter_k<<<8, 1024, scatter_smem>>>(d_out, osz);
}

// round 9
// speedup vs baseline: 1.7131x; 1.0029x over previous
#include <cuda_runtime.h>
#include <math.h>
#include <stdint.h>

#define Bb 8
#define Nn 1024
#define HIDD 256
#define HEADS 8
#define DHH 32
#define KPOOL 512
#define EPER 16384
#define INVKEY (KPOOL*KPOOL)      // 262144
#define BINS (INVKEY+1)           // 262145
#define CHUNK 2048
#define NCH 129                   // ceil(BINS/CHUNK)

// ---------------- scratch (static device globals; no runtime alloc) -------------
__device__ float g_q  [Bb*Nn*HIDD];        // Q; later reused as encoder output
__device__ float g_kT [Bb*HEADS*DHH*Nn];   // [b,h,d,n]
__device__ float g_vT [Bb*HEADS*DHH*Nn];   // [b,h,d,n]
__device__ float g_att[Bb*Nn*HIDD];
__device__ float g_sval[Bb*Nn];
__device__ int   g_perm[Bb*KPOOL];
__device__ float g_vals[Bb*KPOOL];
__device__ int   g_nmap[Bb*Nn];
__device__ unsigned g_key[Bb*EPER];
__device__ int   g_nu[Bb*EPER];
__device__ int   g_nv[Bb*EPER];
__device__ unsigned g_cnt  [Bb*BINS];
__device__ unsigned g_scan [Bb*BINS];
__device__ unsigned g_chunk  [Bb*NCH];
__device__ unsigned g_chunkEx[Bb*NCH];
__device__ int   g_is64;

// output layout (elements, concatenated in reference return order)
#define OFF_ENC   ((long long)0)
#define OFF_SUBX  ((long long)2097152)
#define OFF_EDGE  ((long long)3145728)
#define OFF_PERM  ((long long)3407872)
#define OFF_VALID ((long long)3411968)

__device__ __forceinline__ void st_out(void* out, long long idx, float v,
                                       long long osz) {
    if (idx < 0 || idx >= osz) return;
    if (g_is64) ((double*)out)[idx] = (double)v;
    else        ((float*) out)[idx] = v;
}

__device__ __forceinline__ void cpa16(uint32_t dst, const void* src) {
    asm volatile("cp.async.cg.shared.global [%0], [%1], 16;\n"
                 :: "r"(dst), "l"(src));
}

// ---------------- input dtype probe ---------------------------------------------
__global__ void detect_k(const int* __restrict__ e32) {
    g_is64 = (e32[1] == 0 && e32[3] == 0 && e32[5] == 0 && e32[7] == 0) ? 1 : 0;
}

// ---------------- GEMM: C[M,256] = A[M,256] @ W[256,256] ------------------------
// MODE 0: row-major store.  MODE 1: store transposed to [b,h,d,n].
// DST: 0=g_q  1=g_kT  2=g_vT  3=g_q + packed copy to out (encoder result).
template<int MODE, int DST>
__global__ void sgemm_k(const float* __restrict__ A_in, const float* __restrict__ W,
                        void* __restrict__ out, long long osz) {
    const float* A = (A_in != nullptr) ? A_in : g_att;
    float* C = (DST == 1) ? g_kT : (DST == 2) ? g_vT : g_q;
    __shared__ float As[16][65];
    __shared__ float Ws[16][64];
    const int bm = blockIdx.x * 64, bn = blockIdx.y * 64;
    const int tid = threadIdx.x;
    const int tx = tid & 15, ty = tid >> 4;
    float acc[4][4];
#pragma unroll
    for (int i = 0; i < 4; i++)
#pragma unroll
        for (int j = 0; j < 4; j++) acc[i][j] = 0.f;

    for (int kk = 0; kk < HIDD; kk += 16) {
        {
            int m = tid >> 2, kq = tid & 3;
            float4 av = *(const float4*)&A[(size_t)(bm + m) * HIDD + kk + kq * 4];
            As[kq*4+0][m] = av.x; As[kq*4+1][m] = av.y;
            As[kq*4+2][m] = av.z; As[kq*4+3][m] = av.w;
        }
        {
            int k = tid >> 4, nq = tid & 15;
            *(float4*)&Ws[k][nq*4] =
                *(const float4*)&W[(size_t)(kk + k) * HIDD + bn + nq * 4];
        }
        __syncthreads();
#pragma unroll
        for (int k = 0; k < 16; k++) {
            float a0 = As[k][ty*4+0], a1 = As[k][ty*4+1];
            float a2 = As[k][ty*4+2], a3 = As[k][ty*4+3];
            float4 b4 = *(float4*)&Ws[k][tx*4];
            acc[0][0] += a0*b4.x; acc[0][1] += a0*b4.y; acc[0][2] += a0*b4.z; acc[0][3] += a0*b4.w;
            acc[1][0] += a1*b4.x; acc[1][1] += a1*b4.y; acc[1][2] += a1*b4.z; acc[1][3] += a1*b4.w;
            acc[2][0] += a2*b4.x; acc[2][1] += a2*b4.y; acc[2][2] += a2*b4.z; acc[2][3] += a2*b4.w;
            acc[3][0] += a3*b4.x; acc[3][1] += a3*b4.y; acc[3][2] += a3*b4.z; acc[3][3] += a3*b4.w;
        }
        __syncthreads();
    }
    if (MODE == 0) {
#pragma unroll
        for (int i = 0; i < 4; i++) {
            int row = bm + ty*4 + i;
            float4 v = make_float4(acc[i][0], acc[i][1], acc[i][2], acc[i][3]);
            *(float4*)&C[(size_t)row * HIDD + bn + tx*4] = v;
            if (DST == 3) {
                long long base = (long long)row * HIDD + bn + tx*4;
#pragma unroll
                for (int j = 0; j < 4; j++)
                    st_out(out, OFF_ENC + base + j, acc[i][j], osz);
            }
        }
    } else {
#pragma unroll
        for (int i = 0; i < 4; i++) {
            int row = bm + ty*4 + i;
            int b = row >> 10, n = row & 1023;
#pragma unroll
            for (int j = 0; j < 4; j++) {
                int col = bn + tx*4 + j;
                int h = col >> 5, d = col & 31;
                C[(size_t)(((b << 3) + h) * DHH + d) * Nn + n] = acc[i][j];
            }
        }
    }
}

// ---------------- flash attention -----------------------------------------------
// Single-buffered cp.async (smem 54KB) + launch_bounds(256,3) -> 3 blocks/SM,
// 24 warps/SM. Compute arithmetic is verbatim round-4 (bit-identical output).
#define KVP 132
__global__ void __launch_bounds__(256, 3) attn_k(const float* __restrict__ dist) {
    extern __shared__ float sm[];
    float* Qs = sm;                  // [32][32]
    float* KT = sm + 1024;           // [32][KVP]
    float* VT = KT + 32*KVP;         // [32][KVP]
    float* pb = VT + 32*KVP;         // [8][4][128]
    const int bh = blockIdx.x;            // b*8+h
    const int b = bh >> 3, h = bh & 7;
    const int qbase = blockIdx.y * 32;
    const int tid = threadIdx.x, lane = tid & 31, warp = tid >> 5;
    const int r0 = warp * 4;
    const int cd = tid >> 5;              // d-slice base for loads
    const int ck = (tid & 31) * 4;        // k offset (floats)

    // issue tile-0 K/V loads (async, no register transit)
#pragma unroll
    for (int i = 0; i < 4; i++) {
        int d = cd + i * 8;
        size_t goff = ((size_t)(bh * DHH) + d) * Nn + ck;
        cpa16((uint32_t)__cvta_generic_to_shared(KT + d*KVP + ck), &g_kT[goff]);
        cpa16((uint32_t)__cvta_generic_to_shared(VT + d*KVP + ck), &g_vT[goff]);
    }
    asm volatile("cp.async.commit_group;\n" ::: "memory");
    {   // load Q tile [32 rows][32 dims]
        int rl = tid >> 3, dq = tid & 7;
        *(float4*)&Qs[rl*32 + dq*4] =
            *(const float4*)&g_q[((size_t)(b * Nn) + (qbase + rl)) * HIDD + h * DHH + dq * 4];
    }

    float acc[4]   = {0.f, 0.f, 0.f, 0.f};
    float lpart[4] = {0.f, 0.f, 0.f, 0.f};
    const float isq = 0.17677669529663687f; // 1/sqrt(32)

    for (int kt = 0; kt < 8; kt++) {
        const int k0 = kt * 128;

        // dist bias (independent of smem) — issue before the wait to hide L2 latency
        float4 dv[4];
#pragma unroll
        for (int r = 0; r < 4; r++)
            dv[r] = *(const float4*)&dist[((size_t)(b * Nn + qbase + r0 + r)) * Nn + k0 + lane * 4];

        asm volatile("cp.async.wait_group 0;\n" ::: "memory");
        __syncthreads();   // tile kt visible to all warps

        // ---- compute below is verbatim round-4 arithmetic ----
        float4 s[4];
#pragma unroll
        for (int r = 0; r < 4; r++) s[r] = make_float4(0.f, 0.f, 0.f, 0.f);
#pragma unroll
        for (int d4 = 0; d4 < 8; d4++) {
            float4 qv0 = *(float4*)&Qs[(r0+0)*32 + d4*4];
            float4 qv1 = *(float4*)&Qs[(r0+1)*32 + d4*4];
            float4 qv2 = *(float4*)&Qs[(r0+2)*32 + d4*4];
            float4 qv3 = *(float4*)&Qs[(r0+3)*32 + d4*4];
            const float* q0p = (const float*)&qv0;
            const float* q1p = (const float*)&qv1;
            const float* q2p = (const float*)&qv2;
            const float* q3p = (const float*)&qv3;
#pragma unroll
            for (int dd = 0; dd < 4; dd++) {
                float4 kv = *(float4*)&KT[(d4*4+dd)*KVP + lane*4];
                float q0 = q0p[dd], q1 = q1p[dd], q2 = q2p[dd], q3 = q3p[dd];
                s[0].x += q0*kv.x; s[0].y += q0*kv.y; s[0].z += q0*kv.z; s[0].w += q0*kv.w;
                s[1].x += q1*kv.x; s[1].y += q1*kv.y; s[1].z += q1*kv.z; s[1].w += q1*kv.w;
                s[2].x += q2*kv.x; s[2].y += q2*kv.y; s[2].z += q2*kv.z; s[2].w += q2*kv.w;
                s[3].x += q3*kv.x; s[3].y += q3*kv.y; s[3].z += q3*kv.z; s[3].w += q3*kv.w;
            }
        }

#pragma unroll
        for (int r = 0; r < 4; r++) {
            float4 p4;
            p4.x = __expf(fmaf(s[r].x, isq, dv[r].x));
            p4.y = __expf(fmaf(s[r].y, isq, dv[r].y));
            p4.z = __expf(fmaf(s[r].z, isq, dv[r].z));
            p4.w = __expf(fmaf(s[r].w, isq, dv[r].w));
            lpart[r] += (p4.x + p4.y) + (p4.z + p4.w);
            *(float4*)&pb[(warp*4 + r)*128 + lane*4] = p4;
        }
        __syncwarp();

#pragma unroll
        for (int k4 = 0; k4 < 32; k4++) {
            float4 vv = *(float4*)&VT[lane*KVP + k4*4];
            float4 p0 = *(float4*)&pb[(warp*4+0)*128 + k4*4];
            float4 p1 = *(float4*)&pb[(warp*4+1)*128 + k4*4];
            float4 p2 = *(float4*)&pb[(warp*4+2)*128 + k4*4];
            float4 p3 = *(float4*)&pb[(warp*4+3)*128 + k4*4];
            acc[0] += p0.x*vv.x + p0.y*vv.y + p0.z*vv.z + p0.w*vv.w;
            acc[1] += p1.x*vv.x + p1.y*vv.y + p1.z*vv.z + p1.w*vv.w;
            acc[2] += p2.x*vv.x + p2.y*vv.y + p2.z*vv.z + p2.w*vv.w;
            acc[3] += p3.x*vv.x + p3.y*vv.y + p3.z*vv.z + p3.w*vv.w;
        }

        // all warps done reading KT/VT -> safe to issue next tile into same buffer
        __syncthreads();
        if (kt < 7) {
#pragma unroll
            for (int i = 0; i < 4; i++) {
                int d = cd + i * 8;
                size_t goff = ((size_t)(bh * DHH) + d) * Nn + (k0 + 128) + ck;
                cpa16((uint32_t)__cvta_generic_to_shared(KT + d*KVP + ck), &g_kT[goff]);
                cpa16((uint32_t)__cvta_generic_to_shared(VT + d*KVP + ck), &g_vT[goff]);
            }
            asm volatile("cp.async.commit_group;\n" ::: "memory");
        }
    }
    // final: reduce l across lanes once per row, normalize, store
#pragma unroll
    for (int r = 0; r < 4; r++) {
        float l = lpart[r];
#pragma unroll
        for (int o = 16; o; o >>= 1) l += __shfl_xor_sync(0xffffffffu, l, o);
        int row = qbase + r0 + r;
        g_att[((size_t)(b * Nn) + row) * HIDD + h * DHH + lane] = acc[r] / l;
    }
}
#define ATTN_SMEM ((1024 + 2*32*KVP + 8*4*128) * (int)sizeof(float))

// ---------------- tanh projection scores ---------------------------------------
__global__ void score_k(const float* __restrict__ w) {
    int gw = (blockIdx.x * blockDim.x + threadIdx.x) >> 5;
    int lane = threadIdx.x & 31;
    if (gw >= Bb * Nn) return;
    float nw = 0.f, dot = 0.f;
#pragma unroll
    for (int i = 0; i < 8; i++) {
        float wv = w[lane + i * 32];
        nw += wv * wv;
        dot += wv * g_q[(size_t)gw * HIDD + lane + i * 32];
    }
#pragma unroll
    for (int o = 16; o; o >>= 1) {
        nw  += __shfl_xor_sync(0xffffffffu, nw, o);
        dot += __shfl_xor_sync(0xffffffffu, dot, o);
    }
    if (lane == 0) g_sval[gw] = tanhf(dot / sqrtf(nw));
}

// ---------------- per-graph top-k (full bitonic sort of 1024) -------------------
__global__ void topk_k(void* __restrict__ out, long long osz) {
    __shared__ unsigned long long keys[1024];
    const int b = blockIdx.x, t = threadIdx.x;
    float s = g_sval[b * Nn + t];
    unsigned u = __float_as_uint(s);
    u = (u & 0x80000000u) ? ~u : (u | 0x80000000u);
    u = ~u;
    keys[t] = ((unsigned long long)u << 32) | (unsigned)t;
    __syncthreads();
    for (int k = 2; k <= 1024; k <<= 1) {
        for (int j = k >> 1; j > 0; j >>= 1) {
            int ixj = t ^ j;
            if (ixj > t) {
                bool up = ((t & k) == 0);
                unsigned long long a = keys[t], bv = keys[ixj];
                if ((a > bv) == up) { keys[t] = bv; keys[ixj] = a; }
            }
            __syncthreads();
        }
    }
    g_nmap[b * Nn + t] = -1;
    __syncthreads();
    if (t < KPOOL) {
        int idx = (int)(keys[t] & 0xffffffffu);
        g_perm[b * KPOOL + t] = idx;
        g_vals[b * KPOOL + t] = g_sval[b * Nn + idx];
        g_nmap[b * Nn + idx] = t;
        st_out(out, OFF_PERM + b * KPOOL + t, (float)idx, osz);
    }
}

// ---------------- gated gather sub_x --------------------------------------------
__global__ void subx_k(void* __restrict__ out, long long osz) {
    long long idx = (long long)blockIdx.x * blockDim.x + threadIdx.x;
    int c = (int)(idx & 255);
    int r = (int)((idx >> 8) & 511);
    int b = (int)(idx >> 17);
    int p = g_perm[b * KPOOL + r];
    float v = g_q[((size_t)(b * Nn) + p) * HIDD + c] * g_vals[b * KPOOL + r];
    st_out(out, OFF_SUBX + idx, v, osz);
}

// ---------------- edge pipeline --------------------------------------------------
__global__ void zero_k() {
    int i = blockIdx.x * blockDim.x + threadIdx.x;
    if (i < Bb * BINS) g_cnt[i] = 0u;
}

__global__ void edge_k(const void* __restrict__ ei) {
    int e = blockIdx.x * blockDim.x + threadIdx.x;
    if (e >= Bb * EPER) return;
    int b = e >> 14;
    long long sv, dvv;
    if (g_is64) {
        const long long* p = (const long long*)ei;
        sv = p[e]; dvv = p[Bb * EPER + e];
    } else {
        const int* p = (const int*)ei;
        sv = p[e]; dvv = p[Bb * EPER + e];
    }
    int ls = (int)(sv - (long long)b * Nn);
    int ld = (int)(dvv - (long long)b * Nn);
    bool inr = (ls >= 0) && (ls < Nn) && (ld >= 0) && (ld < Nn);
    int nu = inr ? g_nmap[b * Nn + ls] : -1;
    int nv = inr ? g_nmap[b * Nn + ld] : -1;
    bool valid = (nu >= 0) && (nv >= 0);
    unsigned key = valid ? (unsigned)(nu * KPOOL + nv) : (unsigned)INVKEY;
    g_key[e] = key; g_nu[e] = nu; g_nv[e] = nv;
    atomicAdd(&g_cnt[(size_t)b * BINS + key], 1u);
}

__global__ void scan1_k() {
    __shared__ unsigned sh[1024];
    const int b = blockIdx.x, c = blockIdx.y, t = threadIdx.x;
    int i0 = c * CHUNK + t * 2;
    unsigned v0 = (i0     < BINS) ? g_cnt[(size_t)b * BINS + i0]     : 0u;
    unsigned v1 = (i0 + 1 < BINS) ? g_cnt[(size_t)b * BINS + i0 + 1] : 0u;
    sh[t] = v0 + v1;
    __syncthreads();
    for (int off = 1; off < 1024; off <<= 1) {
        unsigned x = (t >= off) ? sh[t - off] : 0u;
        __syncthreads();
        sh[t] += x;
        __syncthreads();
    }
    unsigned excl = t ? sh[t - 1] : 0u;
    if (i0     < BINS) g_scan[(size_t)b * BINS + i0]     = excl;
    if (i0 + 1 < BINS) g_scan[(size_t)b * BINS + i0 + 1] = excl + v0;
    if (t == 1023) g_chunk[b * NCH + c] = sh[1023];
}

__global__ void scan2_k() {
    int b = threadIdx.x;
    if (b >= Bb) return;
    unsigned run = 0;
    for (int c = 0; c < NCH; c++) {
        unsigned v = g_chunk[b * NCH + c];
        g_chunkEx[b * NCH + c] = run;
        run += v;
    }
}

// dynamic smem: [0,16384) keys, [16384,17408) scan
__global__ void scatter_k(void* __restrict__ out, long long osz) {
    extern __shared__ unsigned sdyn[];
    unsigned* skey = sdyn;
    unsigned* sh   = sdyn + EPER;
    const int b = blockIdx.x, t = threadIdx.x;
    const int gb = b * EPER;
#pragma unroll
    for (int u = 0; u < 16; u++) skey[u * 1024 + t] = g_key[gb + u * 1024 + t];
    __syncthreads();

    const int i0 = t * 16;
    unsigned cinv = 0;
#pragma unroll
    for (int u = 0; u < 16; u++) cinv += (skey[i0 + u] == (unsigned)INVKEY);
    sh[t] = cinv;
    __syncthreads();
    for (int off = 1; off < 1024; off <<= 1) {
        unsigned x = (t >= off) ? sh[t - off] : 0u;
        __syncthreads();
        sh[t] += x;
        __syncthreads();
    }
    unsigned invBase = t ? sh[t - 1] : 0u;
    unsigned nValid = g_scan[(size_t)b * BINS + INVKEY] + g_chunkEx[b * NCH + INVKEY / CHUNK];
    unsigned run = invBase;
    for (int u = 0; u < 16; u++) {
        int i = i0 + u;
        unsigned key = skey[i];
        bool valid = (key != (unsigned)INVKEY);
        unsigned pos;
        if (!valid) {
            pos = nValid + run; run++;
        } else {
            unsigned base = g_scan[(size_t)b * BINS + key] + g_chunkEx[b * NCH + key / CHUNK];
            unsigned cnt  = g_cnt[(size_t)b * BINS + key];
            unsigned rank = 0;
            if (cnt > 1) {   // rare collisions: stable within-bucket rank (smem scan)
                for (int j = 0; j < i; j++) rank += (skey[j] == key);
            }
            pos = base + rank;
        }
        int nu = g_nu[gb + i], nv = g_nv[gb + i];
        st_out(out, OFF_EDGE + (long long)(b * 2 + 0) * EPER + pos,
               valid ? (float)nu : -1.0f, osz);
        st_out(out, OFF_EDGE + (long long)(b * 2 + 1) * EPER + pos,
               valid ? (float)nv : -1.0f, osz);
        st_out(out, OFF_VALID + (long long)b * EPER + pos,
               valid ? 1.0f : 0.0f, osz);
    }
}

// ---------------- launch ---------------------------------------------------------
extern "C" void kernel_launch(void* const* d_in, const int* in_sizes, int n_in,
                              void* d_out, int out_size) {
    const float* x    = (const float*)d_in[0];
    const void*  ei   = d_in[1];
    const float* dist = (const float*)d_in[3];
    const float* Wq   = (const float*)d_in[5];
    const float* Wk   = (const float*)d_in[6];
    const float* Wv   = (const float*)d_in[7];
    const float* Wo   = (const float*)d_in[8];
    const float* tw   = (const float*)d_in[9];
    long long osz = (long long)out_size;

    dim3 gG(128, 4);
    sgemm_k<0,0><<<gG, 256>>>(x, Wq, nullptr, 0);   // 1st: Q -> g_q
    sgemm_k<1,1><<<gG, 256>>>(x, Wk, nullptr, 0);   // 2nd: K -> g_kT
    sgemm_k<1,2><<<gG, 256>>>(x, Wv, nullptr, 0);   // 3rd: V -> g_vT

    cudaFuncSetAttribute(attn_k, cudaFuncAttributeMaxDynamicSharedMemorySize,
                         ATTN_SMEM);
    attn_k<<<dim3(64, 32), 256, ATTN_SMEM>>>(dist); // 4th launch -> ncu slot

    detect_k<<<1, 1>>>((const int*)ei);             // needed before st_out users

    sgemm_k<0,3><<<gG, 256>>>(nullptr, Wo, d_out, osz); // -> g_q + out (fused pack)

    zero_k<<<2049, 1024>>>();
    score_k<<<1024, 256>>>(tw);
    topk_k<<<8, 1024>>>(d_out, osz);
    subx_k<<<4096, 256>>>(d_out, osz);
    edge_k<<<512, 256>>>(ei);
    scan1_k<<<dim3(8, 129), 1024>>>();
    scan2_k<<<1, 32>>>();

    const int scatter_smem = (EPER + 1024) * (int)sizeof(unsigned);
    cudaFuncSetAttribute(scatter_k, cudaFuncAttributeMaxDynamicSharedMemorySize,
                         scatter_smem);
    scatter_k<<<8, 1024, scatter_smem>>>(d_out, osz);
}

// round 10
// speedup vs baseline: 1.8294x; 1.0679x over previous
#include <cuda_runtime.h>
#include <math.h>
#include <stdint.h>

#define Bb 8
#define Nn 1024
#define HIDD 256
#define HEADS 8
#define DHH 32
#define KPOOL 512
#define EPER 16384
#define INVKEY (KPOOL*KPOOL)      // 262144
#define BINS (INVKEY+1)           // 262145
#define CHUNK 2048
#define NCH 129                   // ceil(BINS/CHUNK)

// ---------------- scratch (static device globals; no runtime alloc) -------------
__device__ float g_q  [Bb*Nn*HIDD];        // Q; later reused as encoder output
__device__ float g_kT [Bb*HEADS*DHH*Nn];   // [b,h,d,n]
__device__ float g_vT [Bb*HEADS*DHH*Nn];   // [b,h,d,n]
__device__ float g_att[Bb*Nn*HIDD];
__device__ float g_sval[Bb*Nn];
__device__ int   g_perm[Bb*KPOOL];
__device__ float g_vals[Bb*KPOOL];
__device__ int   g_nmap[Bb*Nn];
__device__ unsigned g_key[Bb*EPER];
__device__ int   g_nu[Bb*EPER];
__device__ int   g_nv[Bb*EPER];
__device__ unsigned g_cnt  [Bb*BINS];
__device__ unsigned g_scan [Bb*BINS];
__device__ unsigned g_chunk  [Bb*NCH];
__device__ unsigned g_chunkEx[Bb*NCH];
__device__ int   g_is64;

// output layout (elements, concatenated in reference return order)
#define OFF_ENC   ((long long)0)
#define OFF_SUBX  ((long long)2097152)
#define OFF_EDGE  ((long long)3145728)
#define OFF_PERM  ((long long)3407872)
#define OFF_VALID ((long long)3411968)

__device__ __forceinline__ void st_out(void* out, long long idx, float v,
                                       long long osz) {
    if (idx < 0 || idx >= osz) return;
    if (g_is64) ((double*)out)[idx] = (double)v;
    else        ((float*) out)[idx] = v;
}

__device__ __forceinline__ void cpa16(uint32_t dst, const void* src) {
    asm volatile("cp.async.cg.shared.global [%0], [%1], 16;\n"
                 :: "r"(dst), "l"(src));
}

// ---------------- input dtype probe ---------------------------------------------
__global__ void detect_k(const int* __restrict__ e32) {
    g_is64 = (e32[1] == 0 && e32[3] == 0 && e32[5] == 0 && e32[7] == 0) ? 1 : 0;
}

// ---------------- GEMM: C[M,256] = A[M,256] @ W[256,256], 128x64 tile, 8x4 micro -
// MODE 0: row-major store.  MODE 1: store transposed to [b,h,d,n].
// DST: 0=g_q  1=g_kT  2=g_vT  3=g_q + packed copy to out (encoder result).
template<int MODE, int DST>
__global__ void sgemm_k(const float* __restrict__ A_in, const float* __restrict__ W,
                        void* __restrict__ out, long long osz) {
    const float* A = (A_in != nullptr) ? A_in : g_att;
    float* C = (DST == 1) ? g_kT : (DST == 2) ? g_vT : g_q;
    __shared__ float As[16][132];   // [k][m], 128 rows + pad
    __shared__ float Ws[16][64];    // [k][n]
    const int bm = blockIdx.x * 128, bn = blockIdx.y * 64;
    const int tid = threadIdx.x;
    const int tx = tid & 15, ty = tid >> 4;
    float acc[8][4];
#pragma unroll
    for (int i = 0; i < 8; i++)
#pragma unroll
        for (int j = 0; j < 4; j++) acc[i][j] = 0.f;

    for (int kk = 0; kk < HIDD; kk += 16) {
        {   // A tile: 128 rows x 16 k; two float4 per thread
            int kq = tid & 3;
#pragma unroll
            for (int half = 0; half < 2; half++) {
                int m = (tid >> 2) + half * 64;
                float4 av = *(const float4*)&A[(size_t)(bm + m) * HIDD + kk + kq * 4];
                As[kq*4+0][m] = av.x; As[kq*4+1][m] = av.y;
                As[kq*4+2][m] = av.z; As[kq*4+3][m] = av.w;
            }
        }
        {   // W tile: 16 k x 64 n
            int k = tid >> 4, nq = tid & 15;
            *(float4*)&Ws[k][nq*4] =
                *(const float4*)&W[(size_t)(kk + k) * HIDD + bn + nq * 4];
        }
        __syncthreads();
#pragma unroll
        for (int k = 0; k < 16; k++) {
            float4 aA = *(float4*)&As[k][ty*8];
            float4 aB = *(float4*)&As[k][ty*8+4];
            float4 b4 = *(float4*)&Ws[k][tx*4];
            const float* ap = (const float*)&aA;
            const float* bp = (const float*)&aB;
#pragma unroll
            for (int i = 0; i < 4; i++) {
                float a = ap[i];
                acc[i][0] += a*b4.x; acc[i][1] += a*b4.y;
                acc[i][2] += a*b4.z; acc[i][3] += a*b4.w;
            }
#pragma unroll
            for (int i = 0; i < 4; i++) {
                float a = bp[i];
                acc[4+i][0] += a*b4.x; acc[4+i][1] += a*b4.y;
                acc[4+i][2] += a*b4.z; acc[4+i][3] += a*b4.w;
            }
        }
        __syncthreads();
    }
    if (MODE == 0) {
#pragma unroll
        for (int i = 0; i < 8; i++) {
            int row = bm + ty*8 + i;
            float4 v = make_float4(acc[i][0], acc[i][1], acc[i][2], acc[i][3]);
            *(float4*)&C[(size_t)row * HIDD + bn + tx*4] = v;
            if (DST == 3) {
                long long base = (long long)row * HIDD + bn + tx*4;
#pragma unroll
                for (int j = 0; j < 4; j++)
                    st_out(out, OFF_ENC + base + j, acc[i][j], osz);
            }
        }
    } else {
#pragma unroll
        for (int i = 0; i < 8; i++) {
            int row = bm + ty*8 + i;
            int b = row >> 10, n = row & 1023;
#pragma unroll
            for (int j = 0; j < 4; j++) {
                int col = bn + tx*4 + j;
                int h = col >> 5, d = col & 31;
                C[(size_t)(((b << 3) + h) * DHH + d) * Nn + n] = acc[i][j];
            }
        }
    }
}

// ---------------- flash attention: 64-row q-tile, 8 rows/warp -------------------
// smem traffic per row halved vs 4-row version. Per-(row,lane) arithmetic chains
// are verbatim round-4 -> bit-identical output.
#define KVP 132
__global__ void __launch_bounds__(256) attn_k(const float* __restrict__ dist) {
    extern __shared__ float sm[];
    float* Qs = sm;                  // [64][32]
    float* KT = sm + 2048;           // [32][KVP]
    float* VT = KT + 32*KVP;         // [32][KVP]
    float* pb = VT + 32*KVP;         // [8 warps][8 rows][128]
    const int bh = blockIdx.x;            // b*8+h
    const int b = bh >> 3, h = bh & 7;
    const int qbase = blockIdx.y * 64;
    const int tid = threadIdx.x, lane = tid & 31, warp = tid >> 5;
    const int r0 = warp * 8;
    const int cd = tid >> 5;              // d-slice base for loads
    const int ck = (tid & 31) * 4;        // k offset (floats)

    // issue tile-0 K/V loads (async, no register transit)
#pragma unroll
    for (int i = 0; i < 4; i++) {
        int d = cd + i * 8;
        size_t goff = ((size_t)(bh * DHH) + d) * Nn + ck;
        cpa16((uint32_t)__cvta_generic_to_shared(KT + d*KVP + ck), &g_kT[goff]);
        cpa16((uint32_t)__cvta_generic_to_shared(VT + d*KVP + ck), &g_vT[goff]);
    }
    asm volatile("cp.async.commit_group;\n" ::: "memory");
    {   // load Q tile [64 rows][32 dims]: 512 float4, 2 per thread
#pragma unroll
        for (int i = 0; i < 2; i++) {
            int F = tid + i * 256;
            int rl = F >> 3, dq = F & 7;
            *(float4*)&Qs[rl*32 + dq*4] =
                *(const float4*)&g_q[((size_t)(b * Nn) + (qbase + rl)) * HIDD + h * DHH + dq * 4];
        }
    }

    float acc[8]   = {0.f,0.f,0.f,0.f,0.f,0.f,0.f,0.f};
    float lpart[8] = {0.f,0.f,0.f,0.f,0.f,0.f,0.f,0.f};
    const float isq = 0.17677669529663687f; // 1/sqrt(32)

    for (int kt = 0; kt < 8; kt++) {
        const int k0 = kt * 128;

        asm volatile("cp.async.wait_group 0;\n" ::: "memory");
        __syncthreads();   // tile kt visible to all warps

        // QK: 8 rows per pass over d (KT read once per warp per tile)
        float4 s[8];
#pragma unroll
        for (int r = 0; r < 8; r++) s[r] = make_float4(0.f, 0.f, 0.f, 0.f);
#pragma unroll
        for (int d4 = 0; d4 < 8; d4++) {
            float4 qv[8];
#pragma unroll
            for (int r = 0; r < 8; r++)
                qv[r] = *(float4*)&Qs[(r0+r)*32 + d4*4];
#pragma unroll
            for (int dd = 0; dd < 4; dd++) {
                float4 kv = *(float4*)&KT[(d4*4+dd)*KVP + lane*4];
#pragma unroll
                for (int r = 0; r < 8; r++) {
                    float q = ((const float*)&qv[r])[dd];
                    s[r].x += q*kv.x; s[r].y += q*kv.y;
                    s[r].z += q*kv.z; s[r].w += q*kv.w;
                }
            }
        }

        // dist bias (L2-resident), then unnormalized exp, per-lane l partials
#pragma unroll
        for (int r = 0; r < 8; r++) {
            float4 dv = *(const float4*)&dist[((size_t)(b * Nn + qbase + r0 + r)) * Nn + k0 + lane * 4];
            float4 p4;
            p4.x = __expf(fmaf(s[r].x, isq, dv.x));
            p4.y = __expf(fmaf(s[r].y, isq, dv.y));
            p4.z = __expf(fmaf(s[r].z, isq, dv.z));
            p4.w = __expf(fmaf(s[r].w, isq, dv.w));
            lpart[r] += (p4.x + p4.y) + (p4.z + p4.w);
            *(float4*)&pb[(warp*8 + r)*128 + lane*4] = p4;
        }
        __syncwarp();

        // AV: 8 rows per pass over k (VT read once per warp per tile)
#pragma unroll
        for (int k4 = 0; k4 < 32; k4++) {
            float4 vv = *(float4*)&VT[lane*KVP + k4*4];
#pragma unroll
            for (int r = 0; r < 8; r++) {
                float4 p = *(float4*)&pb[(warp*8+r)*128 + k4*4];
                acc[r] += p.x*vv.x + p.y*vv.y + p.z*vv.z + p.w*vv.w;
            }
        }

        // all warps done reading KT/VT -> safe to refill same buffer
        __syncthreads();
        if (kt < 7) {
#pragma unroll
            for (int i = 0; i < 4; i++) {
                int d = cd + i * 8;
                size_t goff = ((size_t)(bh * DHH) + d) * Nn + (k0 + 128) + ck;
                cpa16((uint32_t)__cvta_generic_to_shared(KT + d*KVP + ck), &g_kT[goff]);
                cpa16((uint32_t)__cvta_generic_to_shared(VT + d*KVP + ck), &g_vT[goff]);
            }
            asm volatile("cp.async.commit_group;\n" ::: "memory");
        }
    }
    // final: reduce l across lanes once per row, normalize, store
#pragma unroll
    for (int r = 0; r < 8; r++) {
        float l = lpart[r];
#pragma unroll
        for (int o = 16; o; o >>= 1) l += __shfl_xor_sync(0xffffffffu, l, o);
        int row = qbase + r0 + r;
        g_att[((size_t)(b * Nn) + row) * HIDD + h * DHH + lane] = acc[r] / l;
    }
}
#define ATTN_SMEM ((2048 + 2*32*KVP + 8*8*128) * (int)sizeof(float))

// ---------------- tanh projection scores ---------------------------------------
__global__ void score_k(const float* __restrict__ w) {
    int gw = (blockIdx.x * blockDim.x + threadIdx.x) >> 5;
    int lane = threadIdx.x & 31;
    if (gw >= Bb * Nn) return;
    float nw = 0.f, dot = 0.f;
#pragma unroll
    for (int i = 0; i < 8; i++) {
        float wv = w[lane + i * 32];
        nw += wv * wv;
        dot += wv * g_q[(size_t)gw * HIDD + lane + i * 32];
    }
#pragma unroll
    for (int o = 16; o; o >>= 1) {
        nw  += __shfl_xor_sync(0xffffffffu, nw, o);
        dot += __shfl_xor_sync(0xffffffffu, dot, o);
    }
    if (lane == 0) g_sval[gw] = tanhf(dot / sqrtf(nw));
}

// ---------------- per-graph top-k (full bitonic sort of 1024) -------------------
__global__ void topk_k(void* __restrict__ out, long long osz) {
    __shared__ unsigned long long keys[1024];
    const int b = blockIdx.x, t = threadIdx.x;
    float s = g_sval[b * Nn + t];
    unsigned u = __float_as_uint(s);
    u = (u & 0x80000000u) ? ~u : (u | 0x80000000u);
    u = ~u;
    keys[t] = ((unsigned long long)u << 32) | (unsigned)t;
    __syncthreads();
    for (int k = 2; k <= 1024; k <<= 1) {
        for (int j = k >> 1; j > 0; j >>= 1) {
            int ixj = t ^ j;
            if (ixj > t) {
                bool up = ((t & k) == 0);
                unsigned long long a = keys[t], bv = keys[ixj];
                if ((a > bv) == up) { keys[t] = bv; keys[ixj] = a; }
            }
            __syncthreads();
        }
    }
    g_nmap[b * Nn + t] = -1;
    __syncthreads();
    if (t < KPOOL) {
        int idx = (int)(keys[t] & 0xffffffffu);
        g_perm[b * KPOOL + t] = idx;
        g_vals[b * KPOOL + t] = g_sval[b * Nn + idx];
        g_nmap[b * Nn + idx] = t;
        st_out(out, OFF_PERM + b * KPOOL + t, (float)idx, osz);
    }
}

// ---------------- gated gather sub_x --------------------------------------------
__global__ void subx_k(void* __restrict__ out, long long osz) {
    long long idx = (long long)blockIdx.x * blockDim.x + threadIdx.x;
    int c = (int)(idx & 255);
    int r = (int)((idx >> 8) & 511);
    int b = (int)(idx >> 17);
    int p = g_perm[b * KPOOL + r];
    float v = g_q[((size_t)(b * Nn) + p) * HIDD + c] * g_vals[b * KPOOL + r];
    st_out(out, OFF_SUBX + idx, v, osz);
}

// ---------------- edge pipeline --------------------------------------------------
__global__ void zero_k() {
    int i = blockIdx.x * blockDim.x + threadIdx.x;
    const int n4 = (Bb * BINS) / 4;   // 2097160/4 = 524290
    if (i < n4) ((uint4*)g_cnt)[i] = make_uint4(0u, 0u, 0u, 0u);
}

__global__ void edge_k(const void* __restrict__ ei) {
    int e = blockIdx.x * blockDim.x + threadIdx.x;
    if (e >= Bb * EPER) return;
    int b = e >> 14;
    long long sv, dvv;
    if (g_is64) {
        const long long* p = (const long long*)ei;
        sv = p[e]; dvv = p[Bb * EPER + e];
    } else {
        const int* p = (const int*)ei;
        sv = p[e]; dvv = p[Bb * EPER + e];
    }
    int ls = (int)(sv - (long long)b * Nn);
    int ld = (int)(dvv - (long long)b * Nn);
    bool inr = (ls >= 0) && (ls < Nn) && (ld >= 0) && (ld < Nn);
    int nu = inr ? g_nmap[b * Nn + ls] : -1;
    int nv = inr ? g_nmap[b * Nn + ld] : -1;
    bool valid = (nu >= 0) && (nv >= 0);
    unsigned key = valid ? (unsigned)(nu * KPOOL + nv) : (unsigned)INVKEY;
    g_key[e] = key; g_nu[e] = nu; g_nv[e] = nv;
    atomicAdd(&g_cnt[(size_t)b * BINS + key], 1u);
}

// shfl-based block scan (2 barriers instead of 20)
__global__ void scan1_k() {
    __shared__ unsigned wsum[32];
    const int b = blockIdx.x, c = blockIdx.y, t = threadIdx.x;
    const int lane = t & 31, warp = t >> 5;
    int i0 = c * CHUNK + t * 2;
    unsigned v0 = (i0     < BINS) ? g_cnt[(size_t)b * BINS + i0]     : 0u;
    unsigned v1 = (i0 + 1 < BINS) ? g_cnt[(size_t)b * BINS + i0 + 1] : 0u;
    unsigned s = v0 + v1;
    unsigned incl = s;
#pragma unroll
    for (int o = 1; o < 32; o <<= 1) {
        unsigned n = __shfl_up_sync(0xffffffffu, incl, o);
        if (lane >= o) incl += n;
    }
    if (lane == 31) wsum[warp] = incl;
    __syncthreads();
    if (warp == 0) {
        unsigned wv = wsum[lane];
        unsigned wincl = wv;
#pragma unroll
        for (int o = 1; o < 32; o <<= 1) {
            unsigned n = __shfl_up_sync(0xffffffffu, wincl, o);
            if (lane >= o) wincl += n;
        }
        wsum[lane] = wincl - wv;   // exclusive warp offsets
        if (lane == 31) g_chunk[b * NCH + c] = wincl;   // block total
    }
    __syncthreads();
    unsigned excl = wsum[warp] + (incl - s);
    if (i0     < BINS) g_scan[(size_t)b * BINS + i0]     = excl;
    if (i0 + 1 < BINS) g_scan[(size_t)b * BINS + i0 + 1] = excl + v0;
}

// per-graph scan of NCH chunk totals: one warp per graph
__global__ void scan2_k() {
    const int t = threadIdx.x, lane = t & 31, w = t >> 5;   // w = graph
    if (w >= Bb) return;
    unsigned run = 0;
    for (int base = 0; base < NCH; base += 32) {
        int idx = base + lane;
        unsigned v = (idx < NCH) ? g_chunk[w * NCH + idx] : 0u;
        unsigned incl = v;
#pragma unroll
        for (int o = 1; o < 32; o <<= 1) {
            unsigned n = __shfl_up_sync(0xffffffffu, incl, o);
            if (lane >= o) incl += n;
        }
        if (idx < NCH) g_chunkEx[w * NCH + idx] = run + incl - v;
        run += __shfl_sync(0xffffffffu, incl, 31);
    }
}

// dynamic smem: [0,16384) keys, [16384,17408) scan
__global__ void scatter_k(void* __restrict__ out, long long osz) {
    extern __shared__ unsigned sdyn[];
    unsigned* skey = sdyn;
    unsigned* sh   = sdyn + EPER;
    const int b = blockIdx.x, t = threadIdx.x;
    const int gb = b * EPER;
#pragma unroll
    for (int u = 0; u < 16; u++) skey[u * 1024 + t] = g_key[gb + u * 1024 + t];
    __syncthreads();

    const int i0 = t * 16;
    unsigned cinv = 0;
#pragma unroll
    for (int u = 0; u < 16; u++) cinv += (skey[i0 + u] == (unsigned)INVKEY);
    sh[t] = cinv;
    __syncthreads();
    for (int off = 1; off < 1024; off <<= 1) {
        unsigned x = (t >= off) ? sh[t - off] : 0u;
        __syncthreads();
        sh[t] += x;
        __syncthreads();
    }
    unsigned invBase = t ? sh[t - 1] : 0u;
    unsigned nValid = g_scan[(size_t)b * BINS + INVKEY] + g_chunkEx[b * NCH + INVKEY / CHUNK];
    unsigned run = invBase;
    for (int u = 0; u < 16; u++) {
        int i = i0 + u;
        unsigned key = skey[i];
        bool valid = (key != (unsigned)INVKEY);
        unsigned pos;
        if (!valid) {
            pos = nValid + run; run++;
        } else {
            unsigned base = g_scan[(size_t)b * BINS + key] + g_chunkEx[b * NCH + key / CHUNK];
            unsigned cnt  = g_cnt[(size_t)b * BINS + key];
            unsigned rank = 0;
            if (cnt > 1) {   // rare collisions: stable within-bucket rank (smem scan)
                for (int j = 0; j < i; j++) rank += (skey[j] == key);
            }
            pos = base + rank;
        }
        int nu = g_nu[gb + i], nv = g_nv[gb + i];
        st_out(out, OFF_EDGE + (long long)(b * 2 + 0) * EPER + pos,
               valid ? (float)nu : -1.0f, osz);
        st_out(out, OFF_EDGE + (long long)(b * 2 + 1) * EPER + pos,
               valid ? (float)nv : -1.0f, osz);
        st_out(out, OFF_VALID + (long long)b * EPER + pos,
               valid ? 1.0f : 0.0f, osz);
    }
}

// ---------------- launch ---------------------------------------------------------
extern "C" void kernel_launch(void* const* d_in, const int* in_sizes, int n_in,
                              void* d_out, int out_size) {
    const float* x    = (const float*)d_in[0];
    const void*  ei   = d_in[1];
    const float* dist = (const float*)d_in[3];
    const float* Wq   = (const float*)d_in[5];
    const float* Wk   = (const float*)d_in[6];
    const float* Wv   = (const float*)d_in[7];
    const float* Wo   = (const float*)d_in[8];
    const float* tw   = (const float*)d_in[9];
    long long osz = (long long)out_size;

    dim3 gG(64, 4);
    sgemm_k<0,0><<<gG, 256>>>(x, Wq, nullptr, 0);   // 1st: Q -> g_q
    sgemm_k<1,1><<<gG, 256>>>(x, Wk, nullptr, 0);   // 2nd: K -> g_kT
    sgemm_k<1,2><<<gG, 256>>>(x, Wv, nullptr, 0);   // 3rd: V -> g_vT

    cudaFuncSetAttribute(attn_k, cudaFuncAttributeMaxDynamicSharedMemorySize,
                         ATTN_SMEM);
    attn_k<<<dim3(64, 16), 256, ATTN_SMEM>>>(dist); // 4th launch -> ncu slot

    detect_k<<<1, 1>>>((const int*)ei);             // needed before st_out users

    sgemm_k<0,3><<<gG, 256>>>(nullptr, Wo, d_out, osz); // -> g_q + out (fused pack)

    zero_k<<<513, 1024>>>();
    score_k<<<1024, 256>>>(tw);
    topk_k<<<8, 1024>>>(d_out, osz);
    subx_k<<<4096, 256>>>(d_out, osz);
    edge_k<<<512, 256>>>(ei);
    scan1_k<<<dim3(8, 129), 1024>>>();
    scan2_k<<<1, 256>>>();

    const int scatter_smem = (EPER + 1024) * (int)sizeof(unsigned);
    cudaFuncSetAttribute(scatter_k, cudaFuncAttributeMaxDynamicSharedMemorySize,
                         scatter_smem);
    scatter_k<<<8, 1024, scatter_smem>>>(d_out, osz);
}

// round 11
// speedup vs baseline: 3.7496x; 2.0496x over previous
#include <cuda_runtime.h>
#include <math.h>
#include <stdint.h>

#define Bb 8
#define Nn 1024
#define HIDD 256
#define HEADS 8
#define DHH 32
#define KPOOL 512
#define EPER 16384
#define INVKEY (KPOOL*KPOOL)      // 262144

// ---------------- scratch (static device globals; no runtime alloc) -------------
__device__ float g_q  [Bb*Nn*HIDD];        // Q; later reused as encoder output
__device__ float g_kT [Bb*HEADS*DHH*Nn];   // [b,h,d,n]
__device__ float g_vT [Bb*HEADS*DHH*Nn];   // [b,h,d,n]
__device__ float g_att[Bb*Nn*HIDD];
__device__ float g_sval[Bb*Nn];
__device__ int   g_perm[Bb*KPOOL];
__device__ float g_vals[Bb*KPOOL];
__device__ int   g_nmap[Bb*Nn];
__device__ int   g_is64;

// output layout (elements, concatenated in reference return order)
#define OFF_ENC   ((long long)0)
#define OFF_SUBX  ((long long)2097152)
#define OFF_EDGE  ((long long)3145728)
#define OFF_PERM  ((long long)3407872)
#define OFF_VALID ((long long)3411968)

__device__ __forceinline__ void st_out(void* out, long long idx, float v,
                                       long long osz) {
    if (idx < 0 || idx >= osz) return;
    if (g_is64) ((double*)out)[idx] = (double)v;
    else        ((float*) out)[idx] = v;
}

__device__ __forceinline__ void cpa16(uint32_t dst, const void* src) {
    asm volatile("cp.async.cg.shared.global [%0], [%1], 16;\n"
                 :: "r"(dst), "l"(src));
}

// ---------------- input dtype probe ---------------------------------------------
__global__ void detect_k(const int* __restrict__ e32) {
    g_is64 = (e32[1] == 0 && e32[3] == 0 && e32[5] == 0 && e32[7] == 0) ? 1 : 0;
}

// ---------------- GEMM: C[M,256] = A[M,256] @ W[256,256], 128x64 tile, 8x4 micro -
// MODE 0: row-major store.  MODE 1: store transposed to [b,h,d,n].
// DST: 0=g_q  1=g_kT  2=g_vT  3=g_q + packed copy to out (encoder result).
template<int MODE, int DST>
__global__ void sgemm_k(const float* __restrict__ A_in, const float* __restrict__ W,
                        void* __restrict__ out, long long osz) {
    const float* A = (A_in != nullptr) ? A_in : g_att;
    float* C = (DST == 1) ? g_kT : (DST == 2) ? g_vT : g_q;
    __shared__ float As[16][132];   // [k][m], 128 rows + pad
    __shared__ float Ws[16][64];    // [k][n]
    const int bm = blockIdx.x * 128, bn = blockIdx.y * 64;
    const int tid = threadIdx.x;
    const int tx = tid & 15, ty = tid >> 4;
    float acc[8][4];
#pragma unroll
    for (int i = 0; i < 8; i++)
#pragma unroll
        for (int j = 0; j < 4; j++) acc[i][j] = 0.f;

    for (int kk = 0; kk < HIDD; kk += 16) {
        {   // A tile: 128 rows x 16 k; two float4 per thread
            int kq = tid & 3;
#pragma unroll
            for (int half = 0; half < 2; half++) {
                int m = (tid >> 2) + half * 64;
                float4 av = *(const float4*)&A[(size_t)(bm + m) * HIDD + kk + kq * 4];
                As[kq*4+0][m] = av.x; As[kq*4+1][m] = av.y;
                As[kq*4+2][m] = av.z; As[kq*4+3][m] = av.w;
            }
        }
        {   // W tile: 16 k x 64 n
            int k = tid >> 4, nq = tid & 15;
            *(float4*)&Ws[k][nq*4] =
                *(const float4*)&W[(size_t)(kk + k) * HIDD + bn + nq * 4];
        }
        __syncthreads();
#pragma unroll
        for (int k = 0; k < 16; k++) {
            float4 aA = *(float4*)&As[k][ty*8];
            float4 aB = *(float4*)&As[k][ty*8+4];
            float4 b4 = *(float4*)&Ws[k][tx*4];
            const float* ap = (const float*)&aA;
            const float* bp = (const float*)&aB;
#pragma unroll
            for (int i = 0; i < 4; i++) {
                float a = ap[i];
                acc[i][0] += a*b4.x; acc[i][1] += a*b4.y;
                acc[i][2] += a*b4.z; acc[i][3] += a*b4.w;
            }
#pragma unroll
            for (int i = 0; i < 4; i++) {
                float a = bp[i];
                acc[4+i][0] += a*b4.x; acc[4+i][1] += a*b4.y;
                acc[4+i][2] += a*b4.z; acc[4+i][3] += a*b4.w;
            }
        }
        __syncthreads();
    }
    if (MODE == 0) {
#pragma unroll
        for (int i = 0; i < 8; i++) {
            int row = bm + ty*8 + i;
            float4 v = make_float4(acc[i][0], acc[i][1], acc[i][2], acc[i][3]);
            *(float4*)&C[(size_t)row * HIDD + bn + tx*4] = v;
            if (DST == 3) {
                long long base = (long long)row * HIDD + bn + tx*4;
#pragma unroll
                for (int j = 0; j < 4; j++)
                    st_out(out, OFF_ENC + base + j, acc[i][j], osz);
            }
        }
    } else {
#pragma unroll
        for (int i = 0; i < 8; i++) {
            int row = bm + ty*8 + i;
            int b = row >> 10, n = row & 1023;
#pragma unroll
            for (int j = 0; j < 4; j++) {
                int col = bn + tx*4 + j;
                int h = col >> 5, d = col & 31;
                C[(size_t)(((b << 3) + h) * DHH + d) * Nn + n] = acc[i][j];
            }
        }
    }
}

// ---------------- flash attention: 64-row q-tile, 8 rows/warp, 3 blocks/SM ------
// Arithmetic chains per (row,lane) verbatim round-4 -> bit-identical output.
#define KVP 132
__global__ void __launch_bounds__(256, 3) attn_k(const float* __restrict__ dist) {
    extern __shared__ float sm[];
    float* Qs = sm;                  // [64][32]
    float* KT = sm + 2048;           // [32][KVP]
    float* VT = KT + 32*KVP;         // [32][KVP]
    float* pb = VT + 32*KVP;         // [8 warps][8 rows][128]
    const int bh = blockIdx.x;            // b*8+h
    const int b = bh >> 3, h = bh & 7;
    const int qbase = blockIdx.y * 64;
    const int tid = threadIdx.x, lane = tid & 31, warp = tid >> 5;
    const int r0 = warp * 8;
    const int cd = tid >> 5;              // d-slice base for loads
    const int ck = (tid & 31) * 4;        // k offset (floats)

    // issue tile-0 K/V loads (async, no register transit)
#pragma unroll
    for (int i = 0; i < 4; i++) {
        int d = cd + i * 8;
        size_t goff = ((size_t)(bh * DHH) + d) * Nn + ck;
        cpa16((uint32_t)__cvta_generic_to_shared(KT + d*KVP + ck), &g_kT[goff]);
        cpa16((uint32_t)__cvta_generic_to_shared(VT + d*KVP + ck), &g_vT[goff]);
    }
    asm volatile("cp.async.commit_group;\n" ::: "memory");
    {   // load Q tile [64 rows][32 dims]: 512 float4, 2 per thread
#pragma unroll
        for (int i = 0; i < 2; i++) {
            int F = tid + i * 256;
            int rl = F >> 3, dq = F & 7;
            *(float4*)&Qs[rl*32 + dq*4] =
                *(const float4*)&g_q[((size_t)(b * Nn) + (qbase + rl)) * HIDD + h * DHH + dq * 4];
        }
    }

    float acc[8]   = {0.f,0.f,0.f,0.f,0.f,0.f,0.f,0.f};
    float lpart[8] = {0.f,0.f,0.f,0.f,0.f,0.f,0.f,0.f};
    const float isq = 0.17677669529663687f; // 1/sqrt(32)

    for (int kt = 0; kt < 8; kt++) {
        const int k0 = kt * 128;

        asm volatile("cp.async.wait_group 0;\n" ::: "memory");
        __syncthreads();   // tile kt visible to all warps

        // QK: 8 rows per pass over d; Q via scalar broadcast loads (low reg count)
        float4 s[8];
#pragma unroll
        for (int r = 0; r < 8; r++) s[r] = make_float4(0.f, 0.f, 0.f, 0.f);
#pragma unroll
        for (int d4 = 0; d4 < 8; d4++) {
#pragma unroll
            for (int dd = 0; dd < 4; dd++) {
                float4 kv = *(float4*)&KT[(d4*4+dd)*KVP + lane*4];
#pragma unroll
                for (int r = 0; r < 8; r++) {
                    float q = Qs[(r0+r)*32 + d4*4 + dd];
                    s[r].x += q*kv.x; s[r].y += q*kv.y;
                    s[r].z += q*kv.z; s[r].w += q*kv.w;
                }
            }
        }

        // dist bias (L2-resident), then unnormalized exp, per-lane l partials
#pragma unroll
        for (int r = 0; r < 8; r++) {
            float4 dv = *(const float4*)&dist[((size_t)(b * Nn + qbase + r0 + r)) * Nn + k0 + lane * 4];
            float4 p4;
            p4.x = __expf(fmaf(s[r].x, isq, dv.x));
            p4.y = __expf(fmaf(s[r].y, isq, dv.y));
            p4.z = __expf(fmaf(s[r].z, isq, dv.z));
            p4.w = __expf(fmaf(s[r].w, isq, dv.w));
            lpart[r] += (p4.x + p4.y) + (p4.z + p4.w);
            *(float4*)&pb[(warp*8 + r)*128 + lane*4] = p4;
        }
        __syncwarp();

        // AV: 8 rows per pass over k (VT read once per warp per tile)
#pragma unroll
        for (int k4 = 0; k4 < 32; k4++) {
            float4 vv = *(float4*)&VT[lane*KVP + k4*4];
#pragma unroll
            for (int r = 0; r < 8; r++) {
                float4 p = *(float4*)&pb[(warp*8+r)*128 + k4*4];
                acc[r] += p.x*vv.x + p.y*vv.y + p.z*vv.z + p.w*vv.w;
            }
        }

        // all warps done reading KT/VT -> safe to refill same buffer
        __syncthreads();
        if (kt < 7) {
#pragma unroll
            for (int i = 0; i < 4; i++) {
                int d = cd + i * 8;
                size_t goff = ((size_t)(bh * DHH) + d) * Nn + (k0 + 128) + ck;
                cpa16((uint32_t)__cvta_generic_to_shared(KT + d*KVP + ck), &g_kT[goff]);
                cpa16((uint32_t)__cvta_generic_to_shared(VT + d*KVP + ck), &g_vT[goff]);
            }
            asm volatile("cp.async.commit_group;\n" ::: "memory");
        }
    }
    // final: reduce l across lanes once per row, normalize, store
#pragma unroll
    for (int r = 0; r < 8; r++) {
        float l = lpart[r];
#pragma unroll
        for (int o = 16; o; o >>= 1) l += __shfl_xor_sync(0xffffffffu, l, o);
        int row = qbase + r0 + r;
        g_att[((size_t)(b * Nn) + row) * HIDD + h * DHH + lane] = acc[r] / l;
    }
}
#define ATTN_SMEM ((2048 + 2*32*KVP + 8*8*128) * (int)sizeof(float))

// ---------------- tanh projection scores ---------------------------------------
__global__ void score_k(const float* __restrict__ w) {
    int gw = (blockIdx.x * blockDim.x + threadIdx.x) >> 5;
    int lane = threadIdx.x & 31;
    if (gw >= Bb * Nn) return;
    float nw = 0.f, dot = 0.f;
#pragma unroll
    for (int i = 0; i < 8; i++) {
        float wv = w[lane + i * 32];
        nw += wv * wv;
        dot += wv * g_q[(size_t)gw * HIDD + lane + i * 32];
    }
#pragma unroll
    for (int o = 16; o; o >>= 1) {
        nw  += __shfl_xor_sync(0xffffffffu, nw, o);
        dot += __shfl_xor_sync(0xffffffffu, dot, o);
    }
    if (lane == 0) g_sval[gw] = tanhf(dot / sqrtf(nw));
}

// ---------------- per-graph top-k (full bitonic sort of 1024) -------------------
__global__ void topk_k(void* __restrict__ out, long long osz) {
    __shared__ unsigned long long keys[1024];
    const int b = blockIdx.x, t = threadIdx.x;
    float s = g_sval[b * Nn + t];
    unsigned u = __float_as_uint(s);
    u = (u & 0x80000000u) ? ~u : (u | 0x80000000u);
    u = ~u;
    keys[t] = ((unsigned long long)u << 32) | (unsigned)t;
    __syncthreads();
    for (int k = 2; k <= 1024; k <<= 1) {
        for (int j = k >> 1; j > 0; j >>= 1) {
            int ixj = t ^ j;
            if (ixj > t) {
                bool up = ((t & k) == 0);
                unsigned long long a = keys[t], bv = keys[ixj];
                if ((a > bv) == up) { keys[t] = bv; keys[ixj] = a; }
            }
            __syncthreads();
        }
    }
    g_nmap[b * Nn + t] = -1;
    __syncthreads();
    if (t < KPOOL) {
        int idx = (int)(keys[t] & 0xffffffffu);
        g_perm[b * KPOOL + t] = idx;
        g_vals[b * KPOOL + t] = g_sval[b * Nn + idx];
        g_nmap[b * Nn + idx] = t;
        st_out(out, OFF_PERM + b * KPOOL + t, (float)idx, osz);
    }
}

// ---------------- gated gather sub_x --------------------------------------------
__global__ void subx_k(void* __restrict__ out, long long osz) {
    long long idx = (long long)blockIdx.x * blockDim.x + threadIdx.x;
    int c = (int)(idx & 255);
    int r = (int)((idx >> 8) & 511);
    int b = (int)(idx >> 17);
    int p = g_perm[b * KPOOL + r];
    float v = g_q[((size_t)(b * Nn) + p) * HIDD + c] * g_vals[b * KPOOL + r];
    st_out(out, OFF_SUBX + idx, v, osz);
}

// ---------------- edge pipeline: decode + stable sort + output, one kernel ------
// Per graph: pack (skey:19 | idx:14) into 64-bit keys (strict total order ==
// stable argsort by skey), bitonic sort 16384 in 128KB smem, write coalesced.
__global__ void sort_k(const void* __restrict__ ei, void* __restrict__ out,
                       long long osz) {
    extern __shared__ unsigned long long sk[];   // [16384]
    const int b = blockIdx.x, t = threadIdx.x;

    // decode edges -> keys
    for (int m = 0; m < 16; m++) {
        int idx = m * 1024 + t;
        long long sv, dvv;
        if (g_is64) {
            const long long* p = (const long long*)ei;
            sv = p[b * EPER + idx]; dvv = p[Bb * EPER + b * EPER + idx];
        } else {
            const int* p = (const int*)ei;
            sv = p[b * EPER + idx]; dvv = p[Bb * EPER + b * EPER + idx];
        }
        int ls = (int)(sv - (long long)b * Nn);
        int ld = (int)(dvv - (long long)b * Nn);
        bool inr = (ls >= 0) && (ls < Nn) && (ld >= 0) && (ld < Nn);
        int nu = inr ? g_nmap[b * Nn + ls] : -1;
        int nv = inr ? g_nmap[b * Nn + ld] : -1;
        bool valid = (nu >= 0) && (nv >= 0);
        unsigned skey = valid ? (unsigned)(nu * KPOOL + nv) : (unsigned)INVKEY;
        sk[idx] = ((unsigned long long)skey << 14) | (unsigned)idx;
    }
    __syncthreads();

    // bitonic sort of 16384 keys (ascending)
    for (int k = 2; k <= EPER; k <<= 1) {
        for (int j = k >> 1; j > 0; j >>= 1) {
#pragma unroll 1
            for (int m = 0; m < 8; m++) {
                int ce = m * 1024 + t;
                int i  = ((ce & ~(j - 1)) << 1) | (ce & (j - 1));
                int p2 = i | j;
                bool up = ((i & k) == 0);
                unsigned long long a = sk[i], bb = sk[p2];
                if ((a > bb) == up) { sk[i] = bb; sk[p2] = a; }
            }
            __syncthreads();
        }
    }

    // output (coalesced: slot = m*1024 + t)
    for (int m = 0; m < 16; m++) {
        int slot = m * 1024 + t;
        unsigned skey = (unsigned)(sk[slot] >> 14);
        bool valid = (skey != (unsigned)INVKEY);
        float fnu = valid ? (float)(int)(skey >> 9) : -1.0f;
        float fnv = valid ? (float)(int)(skey & (KPOOL - 1)) : -1.0f;
        st_out(out, OFF_EDGE + (long long)(b * 2 + 0) * EPER + slot, fnu, osz);
        st_out(out, OFF_EDGE + (long long)(b * 2 + 1) * EPER + slot, fnv, osz);
        st_out(out, OFF_VALID + (long long)b * EPER + slot,
               valid ? 1.0f : 0.0f, osz);
    }
}
#define SORT_SMEM (EPER * (int)sizeof(unsigned long long))   // 128 KB

// ---------------- launch ---------------------------------------------------------
extern "C" void kernel_launch(void* const* d_in, const int* in_sizes, int n_in,
                              void* d_out, int out_size) {
    const float* x    = (const float*)d_in[0];
    const void*  ei   = d_in[1];
    const float* dist = (const float*)d_in[3];
    const float* Wq   = (const float*)d_in[5];
    const float* Wk   = (const float*)d_in[6];
    const float* Wv   = (const float*)d_in[7];
    const float* Wo   = (const float*)d_in[8];
    const float* tw   = (const float*)d_in[9];
    long long osz = (long long)out_size;

    dim3 gG(64, 4);
    sgemm_k<0,0><<<gG, 256>>>(x, Wq, nullptr, 0);   // 1st: Q -> g_q
    sgemm_k<1,1><<<gG, 256>>>(x, Wk, nullptr, 0);   // 2nd: K -> g_kT
    sgemm_k<1,2><<<gG, 256>>>(x, Wv, nullptr, 0);   // 3rd: V -> g_vT

    cudaFuncSetAttribute(attn_k, cudaFuncAttributeMaxDynamicSharedMemorySize,
                         ATTN_SMEM);
    attn_k<<<dim3(64, 16), 256, ATTN_SMEM>>>(dist); // 4th launch -> ncu slot

    detect_k<<<1, 1>>>((const int*)ei);             // before st_out users / sort

    sgemm_k<0,3><<<gG, 256>>>(nullptr, Wo, d_out, osz); // -> g_q + out (fused pack)

    score_k<<<1024, 256>>>(tw);
    topk_k<<<8, 1024>>>(d_out, osz);
    subx_k<<<4096, 256>>>(d_out, osz);

    cudaFuncSetAttribute(sort_k, cudaFuncAttributeMaxDynamicSharedMemorySize,
                         SORT_SMEM);
    sort_k<<<Bb, 1024, SORT_SMEM>>>(ei, d_out, osz);
}